// round 13
// baseline (speedup 1.0000x reference)
#include <cuda_runtime.h>
#include <cuda_fp16.h>
#include <math.h>
#include <stdint.h>

// Problem constants
#define BSZ   2
#define SEQ   2048
#define DM    2048
#define NH    16
#define NKV   8
#define HD    128
#define DQK   256

// ---------------------------------------------------------------------------
// Scratch
// ---------------------------------------------------------------------------
__device__ __half g_qe[(size_t)BSZ * NH  * SEQ * DQK];
__device__ __half g_ke[(size_t)BSZ * NH  * SEQ * DQK];
__device__ __half g_vt[(size_t)BSZ * NKV * HD * SEQ];   // [b][kvh][d][T]
__device__ __half g_yh[BSZ * SEQ * NH * HD];
__device__ __half g_xh [BSZ * SEQ * DM];
__device__ __half g_wq [NH  * HD * DM];
__device__ __half g_wk [NKV * HD * DM];
__device__ __half g_wv [NKV * HD * DM];
__device__ __half g_wo [DM * NH * HD];
// phase tables
__device__ float g_cs [SEQ * HD];
__device__ float g_sn [SEQ * HD];
__device__ float g_cd [NH * HD];
__device__ float g_sd [NH * HD];

#define MMA_F16(d, a, b)                                                      \
    asm volatile(                                                             \
        "mma.sync.aligned.m16n8k16.row.col.f32.f16.f16.f32 "                  \
        "{%0,%1,%2,%3},{%4,%5,%6,%7},{%8,%9},{%0,%1,%2,%3};\n"                \
        : "+f"((d)[0]), "+f"((d)[1]), "+f"((d)[2]), "+f"((d)[3])              \
        : "r"((a)[0]), "r"((a)[1]), "r"((a)[2]), "r"((a)[3]),                 \
          "r"((b)[0]), "r"((b)[1]))

#define LDSM_X4(r0, r1, r2, r3, addr)                                         \
    asm volatile("ldmatrix.sync.aligned.m8n8.x4.shared.b16 "                  \
                 "{%0,%1,%2,%3}, [%4];"                                       \
                 : "=r"(r0), "=r"(r1), "=r"(r2), "=r"(r3) : "r"(addr))

// ---------------------------------------------------------------------------
// Prep kernels
// ---------------------------------------------------------------------------
__global__ void f2h_kernel(const float* __restrict__ in,
                           __half* __restrict__ out, int n)
{
    int i = (blockIdx.x * blockDim.x + threadIdx.x) * 4;
    if (i < n) {
        float4 v = *(const float4*)(in + i);
        __half2 h0 = __floats2half2_rn(v.x, v.y);
        __half2 h1 = __floats2half2_rn(v.z, v.w);
        uint2 u;
        u.x = *(uint32_t*)&h0;
        u.y = *(uint32_t*)&h1;
        *(uint2*)(out + i) = u;
    }
}

__global__ void transpose_h_kernel(const float* __restrict__ in,
                                   __half* __restrict__ out, int K, int N)
{
    __shared__ float tile[32][33];
    const int n0 = blockIdx.x * 32;
    const int k0 = blockIdx.y * 32;
    const int tx = threadIdx.x;
    const int ty = threadIdx.y;   // block (32, 8)
    #pragma unroll
    for (int j = 0; j < 32; j += 8)
        tile[ty + j][tx] = in[(size_t)(k0 + ty + j) * N + n0 + tx];
    __syncthreads();
    #pragma unroll
    for (int j = 0; j < 32; j += 8)
        out[(size_t)(n0 + ty + j) * K + k0 + tx] = __float2half(tile[tx][ty + j]);
}

__global__ void angles_kernel(float* __restrict__ cs, float* __restrict__ sn)
{
    const int i = blockIdx.x * blockDim.x + threadIdx.x;
    if (i >= SEQ * HD) return;
    const int d = i & (HD - 1);
    const int t = i >> 7;
    const double TWO_PI  = 6.283185307179586;
    const double INV_2PI = 0.15915494309189535;
    const double f   = exp(-9.210340371976184 * (double)d / 128.0);
    const double ang = (double)t * f;
    const double ar  = ang - floor(ang * INV_2PI) * TWO_PI;
    float sa, ca;
    sincosf((float)ar, &sa, &ca);
    cs[i] = ca;
    sn[i] = sa;
}

__global__ void delta_kernel(const float* __restrict__ delta,
                             float* __restrict__ cd, float* __restrict__ sd)
{
    const int i = blockIdx.x * blockDim.x + threadIdx.x;
    if (i >= NH * HD) return;
    float dl = delta[i];
    dl = fminf(fmaxf(dl, -6.2831855f), 0.0f);
    float s, c;
    sincosf(dl, &s, &c);
    cd[i] = c;
    sd[i] = s;
}

__device__ __forceinline__ float softplus_fast(float x)
{
    if (x > 15.0f) return x;
    return __logf(1.0f + __expf(x));
}

// ---------------------------------------------------------------------------
// fp16 GEMM: 128x128x32 tile, 128 threads (4 warps, warp tile 64x64),
// ldmatrix fragment loads, 3-stage cp.async. Templated epilogue:
//   MODE 0: plain f32 store               (Wo projection -> out)
//   MODE 1: PoPE Q-encode -> half qe      (softplus * cos/sin)
//   MODE 2: PoPE K-encode -> half ke      (2 sibling heads via delta rotation)
//   MODE 3: V transpose   -> half vt[d][T]
// ---------------------------------------------------------------------------
#define GASTR 40
#define G_STG_H (2 * 128 * GASTR)
#define G_STAGES 3
#define GEMM_SMEM_BYTES (G_STAGES * G_STG_H * 2)

template<int MODE>
__global__ void __launch_bounds__(128)
gemm_h_kernel(const __half* __restrict__ A, const __half* __restrict__ B,
              void* __restrict__ Cout, int M, int N, int K,
              const float* __restrict__ cs, const float* __restrict__ sn,
              const float* __restrict__ cd, const float* __restrict__ sd)
{
    extern __shared__ __half smh[];

    const int tid    = threadIdx.x;
    const int wid    = tid >> 5;
    const int lane   = tid & 31;
    const int g      = lane >> 2;
    const int t      = lane & 3;
    const int lane15 = lane & 15;
    const int lanehi = (lane >> 4) * 8;

    const int mbase = (wid & 1) * 64;
    const int nbase = (wid >> 1) * 64;

    const __half* Ag = A + (size_t)blockIdx.y * 128 * K;
    const __half* Bg = B + (size_t)blockIdx.x * 128 * K;

    const uint32_t smb   = (uint32_t)__cvta_generic_to_shared(smh);
    const uint32_t a_off = (uint32_t)((mbase + lane15) * GASTR + lanehi);
    const uint32_t b_off = (uint32_t)((nbase + lane15) * GASTR + lanehi);

    float acc[4][8][4];
    #pragma unroll
    for (int i = 0; i < 4; i++)
        #pragma unroll
        for (int j = 0; j < 8; j++)
            #pragma unroll
            for (int u = 0; u < 4; u++) acc[i][j][u] = 0.0f;

    const int kiters = K / 32;

    auto issue_stage = [&](int s, int it) {
        const int k0 = it * 32;
        unsigned sa = smb + (unsigned)s * (G_STG_H * 2u);
        unsigned sb = sa + 128u * GASTR * 2u;
        #pragma unroll
        for (int j = 0; j < 4; j++) {
            int c = tid + j * 128;              // 0..511
            int r  = c >> 2;                    // 0..127
            int ch = (c & 3) * 8;
            const __half* srca = Ag + (size_t)r * K + k0 + ch;
            asm volatile("cp.async.cg.shared.global [%0], [%1], 16;\n"
                         :: "r"(sa + (unsigned)(r * GASTR + ch) * 2u), "l"(srca));
            const __half* srcb = Bg + (size_t)r * K + k0 + ch;
            asm volatile("cp.async.cg.shared.global [%0], [%1], 16;\n"
                         :: "r"(sb + (unsigned)(r * GASTR + ch) * 2u), "l"(srcb));
        }
        asm volatile("cp.async.commit_group;\n");
    };

    issue_stage(0, 0);
    issue_stage(1, 1);

    for (int it = 0; it < kiters; it++) {
        if (it + 2 < kiters)
            issue_stage((it + 2) % G_STAGES, it + 2);
        else
            asm volatile("cp.async.commit_group;\n");
        asm volatile("cp.async.wait_group 2;\n");
        __syncthreads();

        const uint32_t sa = smb + (uint32_t)(it % G_STAGES) * (G_STG_H * 2u);
        const uint32_t sb = sa + 128u * GASTR * 2u;

        #pragma unroll
        for (int ks = 0; ks < 2; ks++) {
            const int kk = ks * 16;
            uint32_t af[4][4];
            #pragma unroll
            for (int mt = 0; mt < 4; mt++)
                LDSM_X4(af[mt][0], af[mt][1], af[mt][2], af[mt][3],
                        sa + (a_off + mt * 16 * GASTR + kk) * 2u);
            uint32_t bf[8][2];
            #pragma unroll
            for (int p = 0; p < 4; p++) {
                uint32_t r0, r1, r2, r3;
                LDSM_X4(r0, r1, r2, r3,
                        sb + (b_off + p * 16 * GASTR + kk) * 2u);
                bf[2 * p][0]     = r0;
                bf[2 * p + 1][0] = r1;
                bf[2 * p][1]     = r2;
                bf[2 * p + 1][1] = r3;
            }
            #pragma unroll
            for (int mt = 0; mt < 4; mt++)
                #pragma unroll
                for (int nt = 0; nt < 8; nt++)
                    MMA_F16(acc[mt][nt], af[mt], bf[nt]);
        }
        __syncthreads();
    }

    // ------------------------ epilogue ------------------------
    #pragma unroll
    for (int mt = 0; mt < 4; mt++) {
        #pragma unroll
        for (int nt = 0; nt < 8; nt++) {
            const int colbase = blockIdx.x * 128 + nbase + nt * 8 + 2 * t;
            #pragma unroll
            for (int hf = 0; hf < 2; hf++) {
                const int row = blockIdx.y * 128 + mbase + mt * 16 + g + 8 * hf;
                const float v0 = acc[mt][nt][2 * hf];
                const float v1 = acc[mt][nt][2 * hf + 1];

                if (MODE == 0) {
                    *(float2*)((float*)Cout + (size_t)row * N + colbase) =
                        make_float2(v0, v1);
                } else if (MODE == 1) {
                    const int b  = row >> 11;
                    const int tt = row & (SEQ - 1);
                    const int h  = colbase >> 7;
                    const int d  = colbase & (HD - 1);
                    const float mag0 = softplus_fast(v0);
                    const float mag1 = softplus_fast(v1);
                    const float ca0 = cs[(tt << 7) + d];
                    const float sa0 = sn[(tt << 7) + d];
                    const float ca1 = cs[(tt << 7) + d + 1];
                    const float sa1 = sn[(tt << 7) + d + 1];
                    __half* qe = (__half*)Cout;
                    const size_t o = (((size_t)(b * NH + h)) * SEQ + tt) * DQK + d;
                    *(__half2*)(qe + o)      = __floats2half2_rn(mag0 * ca0, mag1 * ca1);
                    *(__half2*)(qe + o + HD) = __floats2half2_rn(mag0 * sa0, mag1 * sa1);
                } else if (MODE == 2) {
                    const int b   = row >> 11;
                    const int tt  = row & (SEQ - 1);
                    const int kvh = colbase >> 7;
                    const int d   = colbase & (HD - 1);
                    const float mag0 = softplus_fast(v0);
                    const float mag1 = softplus_fast(v1);
                    const float ca0 = cs[(tt << 7) + d];
                    const float sa0 = sn[(tt << 7) + d];
                    const float ca1 = cs[(tt << 7) + d + 1];
                    const float sa1 = sn[(tt << 7) + d + 1];
                    __half* ke = (__half*)Cout;
                    #pragma unroll
                    for (int hh = 0; hh < 2; hh++) {
                        const int h = 2 * kvh + hh;
                        const float c0 = cd[(h << 7) + d];
                        const float s0 = sd[(h << 7) + d];
                        const float c1 = cd[(h << 7) + d + 1];
                        const float s1 = sd[(h << 7) + d + 1];
                        const float ck0 = ca0 * c0 - sa0 * s0;
                        const float sk0 = sa0 * c0 + ca0 * s0;
                        const float ck1 = ca1 * c1 - sa1 * s1;
                        const float sk1 = sa1 * c1 + ca1 * s1;
                        const size_t o =
                            (((size_t)(b * NH + h)) * SEQ + tt) * DQK + d;
                        *(__half2*)(ke + o) =
                            __floats2half2_rn(mag0 * ck0, mag1 * ck1);
                        *(__half2*)(ke + o + HD) =
                            __floats2half2_rn(mag0 * sk0, mag1 * sk1);
                    }
                } else {   // MODE 3: V transpose
                    const int b   = row >> 11;
                    const int tt  = row & (SEQ - 1);
                    const int kvh = colbase >> 7;
                    const int d   = colbase & (HD - 1);
                    __half* vt = (__half*)Cout;
                    const size_t o =
                        (((size_t)(b * NKV + kvh)) * HD + d) * SEQ + tt;
                    vt[o]       = __float2half(v0);
                    vt[o + SEQ] = __float2half(v1);
                }
            }
        }
    }
}

// ---------------------------------------------------------------------------
// fp16 causal flash attention. BM=128, BN=64, 256 threads (8 warps x 16 rows).
// QK k=256, PV k=64. V pre-transposed [d][T]. Double-buffered cp.async.
// ---------------------------------------------------------------------------
#define FBM 128
#define FBN 64
#define QSTR 264
#define KSTR 264
#define VSTR 72
#define PSTR 72

#define FL_Q_H (FBM * QSTR)
#define FL_K_H (2 * FBN * KSTR)
#define FL_V_H (2 * HD * VSTR)
#define FL_P_H (FBM * PSTR)
#define FLASH_SMEM_BYTES ((FL_Q_H + FL_K_H + FL_V_H + FL_P_H) * 2)

__global__ void __launch_bounds__(256)
flash_h_kernel(const __half* __restrict__ Qe, const __half* __restrict__ Ke,
               const __half* __restrict__ Vt, __half* __restrict__ Y)
{
    extern __shared__ __half smh[];
    __half* Ps = smh + FL_Q_H + FL_K_H + FL_V_H;

    const int qt = blockIdx.x;
    const int h  = blockIdx.y;
    const int b  = blockIdx.z;
    const int q0 = qt * FBM;

    const int tid    = threadIdx.x;
    const int wid    = tid >> 5;
    const int lane   = tid & 31;
    const int g      = lane >> 2;
    const int t      = lane & 3;
    const int lane15 = lane & 15;
    const int lanehi = (lane >> 4) * 8;
    const int r0     = wid * 16;

    const __half* qbase = Qe + (((size_t)(b * NH + h)) * SEQ + q0) * DQK;
    const __half* kbase = Ke + (((size_t)(b * NH + h)) * SEQ) * DQK;
    const __half* vbase = Vt + ((size_t)(b * NKV + (h >> 1)) * HD) * SEQ;

    const uint32_t smb  = (uint32_t)__cvta_generic_to_shared(smh);
    const uint32_t qs_b = smb;
    const uint32_t ks_b = smb + FL_Q_H * 2u;
    const uint32_t vs_b = smb + (FL_Q_H + FL_K_H) * 2u;
    const uint32_t ps_b = smb + (FL_Q_H + FL_K_H + FL_V_H) * 2u;

    const uint32_t q_off = (uint32_t)((r0 + lane15) * QSTR + lanehi);
    const uint32_t k_off = (uint32_t)(lane15 * KSTR + lanehi);
    const uint32_t v_off = (uint32_t)(lane15 * VSTR + lanehi);
    const uint32_t p_off = (uint32_t)((r0 + lane15) * PSTR + lanehi);

    // Q tile 128x256 halves = 4096 chunks, 16 iters of 256 threads
    {
        #pragma unroll
        for (int l = 0; l < 16; l++) {
            int i = l * 256 + tid;
            int r  = i >> 5;              // 0..127
            int c8 = (i & 31) * 8;
            const __half* src = qbase + (size_t)r * DQK + c8;
            asm volatile("cp.async.cg.shared.global [%0], [%1], 16;\n"
                         :: "r"(qs_b + (unsigned)(r * QSTR + c8) * 2u), "l"(src));
        }
        asm volatile("cp.async.commit_group;\n");
    }

    auto issue_kv = [&](int s, int kt) {
        const int k0 = kt * FBN;
        unsigned ks = ks_b + (unsigned)s * (FBN * KSTR * 2u);
        unsigned vs = vs_b + (unsigned)s * (HD * VSTR * 2u);
        #pragma unroll
        for (int l = 0; l < 8; l++) {       // K: 64x256 halves = 2048 chunks
            int i = l * 256 + tid;
            int r  = i >> 5;                // 0..63
            int c8 = (i & 31) * 8;
            const __half* src = kbase + (size_t)(k0 + r) * DQK + c8;
            asm volatile("cp.async.cg.shared.global [%0], [%1], 16;\n"
                         :: "r"(ks + (unsigned)(r * KSTR + c8) * 2u), "l"(src));
        }
        #pragma unroll
        for (int l = 0; l < 4; l++) {       // V: 128 d x 64 t halves = 1024 chunks
            int i = l * 256 + tid;
            int rd = i >> 3;                // 0..127
            int c8 = (i & 7) * 8;           // 0..56
            const __half* src = vbase + (size_t)rd * SEQ + k0 + c8;
            asm volatile("cp.async.cg.shared.global [%0], [%1], 16;\n"
                         :: "r"(vs + (unsigned)(rd * VSTR + c8) * 2u), "l"(src));
        }
        asm volatile("cp.async.commit_group;\n");
    };

    float m[2]    = { -3.0e38f, -3.0e38f };
    float lsum[2] = { 0.0f, 0.0f };
    float oacc[16][4];
    #pragma unroll
    for (int j = 0; j < 16; j++)
        #pragma unroll
        for (int u = 0; u < 4; u++) oacc[j][u] = 0.0f;

    const float scale = 0.08838834764831845f;
    const int ntl = 2 * qt + 2;

    issue_kv(0, 0);

    for (int kt = 0; kt < ntl; kt++) {
        const int k0 = kt * FBN;
        if (kt + 1 < ntl)
            issue_kv((kt + 1) & 1, kt + 1);
        else
            asm volatile("cp.async.commit_group;\n");
        asm volatile("cp.async.wait_group 1;\n");
        __syncthreads();

        const uint32_t ksb = ks_b + (uint32_t)(kt & 1) * (FBN * KSTR * 2u);
        const uint32_t vsb = vs_b + (uint32_t)(kt & 1) * (HD * VSTR * 2u);

        // ---- S = Q K^T (16x64 per warp, k=256) ----
        float sacc[8][4];
        #pragma unroll
        for (int j = 0; j < 8; j++)
            #pragma unroll
            for (int u = 0; u < 4; u++) sacc[j][u] = 0.0f;

        #pragma unroll
        for (int ks = 0; ks < 16; ks++) {
            const int kk = ks * 16;
            uint32_t a[4];
            LDSM_X4(a[0], a[1], a[2], a[3], qs_b + (q_off + kk) * 2u);
            uint32_t bf[8][2];
            #pragma unroll
            for (int p = 0; p < 4; p++) {
                uint32_t r0r, r1r, r2r, r3r;
                LDSM_X4(r0r, r1r, r2r, r3r,
                        ksb + (k_off + p * 16 * KSTR + kk) * 2u);
                bf[2 * p][0]     = r0r;
                bf[2 * p + 1][0] = r1r;
                bf[2 * p][1]     = r2r;
                bf[2 * p + 1][1] = r3r;
            }
            #pragma unroll
            for (int j = 0; j < 8; j++)
                MMA_F16(sacc[j], a, bf[j]);
        }

        // ---- online softmax (rows r0+g, r0+g+8; warp-local) ----
        const bool diag = (kt >= 2 * qt);
        #pragma unroll
        for (int hf = 0; hf < 2; hf++) {
            const int row = q0 + r0 + g + 8 * hf;
            float v[16];
            float mloc = -3.0e38f;
            #pragma unroll
            for (int j = 0; j < 8; j++) {
                #pragma unroll
                for (int c = 0; c < 2; c++) {
                    int col = k0 + 8 * j + 2 * t + c;
                    float sv = sacc[j][2 * hf + c] * scale;
                    if (diag && col > row) sv = -3.0e38f;
                    v[2 * j + c] = sv;
                    mloc = fmaxf(mloc, sv);
                }
            }
            mloc = fmaxf(mloc, __shfl_xor_sync(0xffffffffu, mloc, 1));
            mloc = fmaxf(mloc, __shfl_xor_sync(0xffffffffu, mloc, 2));
            float mn = fmaxf(m[hf], mloc);
            float alpha = __expf(m[hf] - mn);
            float rs = 0.0f;
            __half2 ph[8];
            #pragma unroll
            for (int j = 0; j < 8; j++) {
                float p0 = __expf(v[2 * j]     - mn);
                float p1 = __expf(v[2 * j + 1] - mn);
                __half2 h2 = __floats2half2_rn(p0, p1);
                ph[j] = h2;
                float2 pr = __half22float2(h2);
                rs += pr.x + pr.y;
            }
            rs += __shfl_xor_sync(0xffffffffu, rs, 1);
            rs += __shfl_xor_sync(0xffffffffu, rs, 2);
            lsum[hf] = lsum[hf] * alpha + rs;
            m[hf] = mn;
            #pragma unroll
            for (int j = 0; j < 16; j++) {
                oacc[j][2 * hf]     *= alpha;
                oacc[j][2 * hf + 1] *= alpha;
            }
            #pragma unroll
            for (int j = 0; j < 8; j++)
                *(__half2*)(Ps + (size_t)(r0 + g + 8 * hf) * PSTR
                            + 8 * j + 2 * t) = ph[j];
        }
        __syncwarp();

        // ---- O += P V (16x128 per warp, k=64) ----
        #pragma unroll
        for (int ks = 0; ks < 4; ks++) {
            const int kk = ks * 16;
            uint32_t a[4];
            LDSM_X4(a[0], a[1], a[2], a[3], ps_b + (p_off + kk) * 2u);
            #pragma unroll
            for (int p = 0; p < 8; p++) {
                uint32_t r0r, r1r, r2r, r3r;
                LDSM_X4(r0r, r1r, r2r, r3r,
                        vsb + (v_off + p * 16 * VSTR + kk) * 2u);
                uint32_t b0[2] = { r0r, r2r };
                uint32_t b1[2] = { r1r, r3r };
                MMA_F16(oacc[2 * p],     a, b0);
                MMA_F16(oacc[2 * p + 1], a, b1);
            }
        }
        __syncthreads();
    }

    // epilogue
    #pragma unroll
    for (int hf = 0; hf < 2; hf++) {
        const int row = q0 + r0 + g + 8 * hf;
        const float inv = 1.0f / lsum[hf];
        __half* yr = Y + ((size_t)b * SEQ + row) * DM + h * HD;
        #pragma unroll
        for (int j = 0; j < 16; j++)
            *(__half2*)(yr + 8 * j + 2 * t) =
                __floats2half2_rn(oacc[j][2 * hf] * inv,
                                  oacc[j][2 * hf + 1] * inv);
    }
}

// ---------------------------------------------------------------------------
// Launch
// ---------------------------------------------------------------------------
extern "C" void kernel_launch(void* const* d_in, const int* in_sizes, int n_in,
                              void* d_out, int out_size)
{
    const float* x     = (const float*)d_in[0];
    const float* Wq    = (const float*)d_in[1];
    const float* Wk    = (const float*)d_in[2];
    const float* Wv    = (const float*)d_in[3];
    const float* Wo    = (const float*)d_in[4];
    const float* delta = (const float*)d_in[5];
    float* out = (float*)d_out;

    float  *cs_, *sn_, *cd_, *sd_;
    __half *qe_, *ke_, *vt_, *yh_, *xh_, *wq_, *wk_, *wv_, *wo_;
    cudaGetSymbolAddress((void**)&qe_, g_qe);
    cudaGetSymbolAddress((void**)&ke_, g_ke);
    cudaGetSymbolAddress((void**)&vt_, g_vt);
    cudaGetSymbolAddress((void**)&yh_, g_yh);
    cudaGetSymbolAddress((void**)&xh_, g_xh);
    cudaGetSymbolAddress((void**)&wq_, g_wq);
    cudaGetSymbolAddress((void**)&wk_, g_wk);
    cudaGetSymbolAddress((void**)&wv_, g_wv);
    cudaGetSymbolAddress((void**)&wo_, g_wo);
    cudaGetSymbolAddress((void**)&cs_, g_cs);
    cudaGetSymbolAddress((void**)&sn_, g_sn);
    cudaGetSymbolAddress((void**)&cd_, g_cd);
    cudaGetSymbolAddress((void**)&sd_, g_sd);

    const int M = BSZ * SEQ;   // 4096

    cudaFuncSetAttribute(gemm_h_kernel<0>,
                         cudaFuncAttributeMaxDynamicSharedMemorySize,
                         GEMM_SMEM_BYTES);
    cudaFuncSetAttribute(gemm_h_kernel<1>,
                         cudaFuncAttributeMaxDynamicSharedMemorySize,
                         GEMM_SMEM_BYTES);
    cudaFuncSetAttribute(gemm_h_kernel<2>,
                         cudaFuncAttributeMaxDynamicSharedMemorySize,
                         GEMM_SMEM_BYTES);
    cudaFuncSetAttribute(gemm_h_kernel<3>,
                         cudaFuncAttributeMaxDynamicSharedMemorySize,
                         GEMM_SMEM_BYTES);
    cudaFuncSetAttribute(flash_h_kernel,
                         cudaFuncAttributeMaxDynamicSharedMemorySize,
                         FLASH_SMEM_BYTES);

    // Launch order places gemm_h_kernel<1> in the ncu capture slot (5th launch).
    {
        int n = BSZ * SEQ * DM;
        f2h_kernel<<<(n / 4 + 255) / 256, 256>>>(x, xh_, n);                     // 1
        dim3 blk(32, 8);
        transpose_h_kernel<<<dim3(DM / 32, DM / 32), blk>>>(Wq, wq_, DM, DM);    // 2
        angles_kernel<<<(SEQ * HD + 255) / 256, 256>>>(cs_, sn_);                // 3
        delta_kernel<<<(NH * HD + 255) / 256, 256>>>(delta, cd_, sd_);           // 4
        // Q projection + fused PoPE encode                                      // 5
        gemm_h_kernel<1><<<dim3(DM / 128, M / 128), 128, GEMM_SMEM_BYTES>>>(
            xh_, wq_, qe_, M, DM, DM, cs_, sn_, cd_, sd_);
        transpose_h_kernel<<<dim3(NKV * HD / 32, DM / 32), blk>>>(Wk, wk_, DM, NKV * HD); // 6
        transpose_h_kernel<<<dim3(NKV * HD / 32, DM / 32), blk>>>(Wv, wv_, DM, NKV * HD); // 7
        // K projection + fused encode (both sibling heads)                      // 8
        gemm_h_kernel<2><<<dim3(NKV * HD / 128, M / 128), 128, GEMM_SMEM_BYTES>>>(
            xh_, wk_, ke_, M, NKV * HD, DM, cs_, sn_, cd_, sd_);
        // V projection + fused transpose                                        // 9
        gemm_h_kernel<3><<<dim3(NKV * HD / 128, M / 128), 128, GEMM_SMEM_BYTES>>>(
            xh_, wv_, vt_, M, NKV * HD, DM, cs_, sn_, cd_, sd_);
        transpose_h_kernel<<<dim3(DM / 32, DM / 32), blk>>>(Wo, wo_, DM, DM);    // 10
    }

    // flash attention                                                           // 11
    flash_h_kernel<<<dim3(SEQ / FBM, NH, BSZ), 256, FLASH_SMEM_BYTES>>>(
        qe_, ke_, vt_, yh_);

    // output projection                                                         // 12
    gemm_h_kernel<0><<<dim3(DM / 128, M / 128), 128, GEMM_SMEM_BYTES>>>(
        yh_, wo_, out, M, DM, DM, cs_, sn_, cd_, sd_);
}

// round 14
// speedup vs baseline: 1.0708x; 1.0708x over previous
#include <cuda_runtime.h>
#include <cuda_fp16.h>
#include <math.h>
#include <stdint.h>

// Problem constants
#define BSZ   2
#define SEQ   2048
#define DM    2048
#define NH    16
#define NKV   8
#define HD    128
#define DQK   256

// ---------------------------------------------------------------------------
// Scratch
// ---------------------------------------------------------------------------
__device__ float  g_q [BSZ * SEQ * NH  * HD];
__device__ float  g_k [BSZ * SEQ * NKV * HD];
__device__ float  g_v [BSZ * SEQ * NKV * HD];
__device__ __half g_qe[(size_t)BSZ * NH  * SEQ * DQK];
__device__ __half g_ke[(size_t)BSZ * NH  * SEQ * DQK];
__device__ __half g_vt[(size_t)BSZ * NKV * HD * SEQ];   // [b][kvh][d][T]
__device__ __half g_yh[BSZ * SEQ * NH * HD];
__device__ __half g_xh [BSZ * SEQ * DM];
__device__ __half g_wq [NH  * HD * DM];
__device__ __half g_wk [NKV * HD * DM];
__device__ __half g_wv [NKV * HD * DM];
__device__ __half g_wo [DM * NH * HD];
// phase tables
__device__ float g_cs [SEQ * HD];
__device__ float g_sn [SEQ * HD];
__device__ float g_cd [NH * HD];
__device__ float g_sd [NH * HD];

#define MMA_F16(d, a, b)                                                      \
    asm volatile(                                                             \
        "mma.sync.aligned.m16n8k16.row.col.f32.f16.f16.f32 "                  \
        "{%0,%1,%2,%3},{%4,%5,%6,%7},{%8,%9},{%0,%1,%2,%3};\n"                \
        : "+f"((d)[0]), "+f"((d)[1]), "+f"((d)[2]), "+f"((d)[3])              \
        : "r"((a)[0]), "r"((a)[1]), "r"((a)[2]), "r"((a)[3]),                 \
          "r"((b)[0]), "r"((b)[1]))

#define LDSM_X4(r0, r1, r2, r3, addr)                                         \
    asm volatile("ldmatrix.sync.aligned.m8n8.x4.shared.b16 "                  \
                 "{%0,%1,%2,%3}, [%4];"                                       \
                 : "=r"(r0), "=r"(r1), "=r"(r2), "=r"(r3) : "r"(addr))

// ---------------------------------------------------------------------------
// Prep kernels
// ---------------------------------------------------------------------------
__global__ void f2h_kernel(const float* __restrict__ in,
                           __half* __restrict__ out, int n)
{
    int i = (blockIdx.x * blockDim.x + threadIdx.x) * 4;
    if (i < n) {
        float4 v = *(const float4*)(in + i);
        __half2 h0 = __floats2half2_rn(v.x, v.y);
        __half2 h1 = __floats2half2_rn(v.z, v.w);
        uint2 u;
        u.x = *(uint32_t*)&h0;
        u.y = *(uint32_t*)&h1;
        *(uint2*)(out + i) = u;
    }
}

__global__ void transpose_h_kernel(const float* __restrict__ in,
                                   __half* __restrict__ out, int K, int N)
{
    __shared__ float tile[32][33];
    const int n0 = blockIdx.x * 32;
    const int k0 = blockIdx.y * 32;
    const int tx = threadIdx.x;
    const int ty = threadIdx.y;   // block (32, 8)
    #pragma unroll
    for (int j = 0; j < 32; j += 8)
        tile[ty + j][tx] = in[(size_t)(k0 + ty + j) * N + n0 + tx];
    __syncthreads();
    #pragma unroll
    for (int j = 0; j < 32; j += 8)
        out[(size_t)(n0 + ty + j) * K + k0 + tx] = __float2half(tile[tx][ty + j]);
}

__global__ void vtrans_kernel(const float* __restrict__ v,
                              __half* __restrict__ vt)
{
    __shared__ float tile[32][33];
    const int t0 = blockIdx.x * 32;
    const int d0 = blockIdx.y * 32;
    const int z  = blockIdx.z;
    const int b  = z / NKV;
    const int kh = z % NKV;
    const int tx = threadIdx.x;
    const int ty = threadIdx.y;   // block (32, 8)
    #pragma unroll
    for (int j = 0; j < 32; j += 8)
        tile[ty + j][tx] =
            v[((size_t)(b * SEQ + t0 + ty + j)) * (NKV * HD) + kh * HD + d0 + tx];
    __syncthreads();
    #pragma unroll
    for (int j = 0; j < 32; j += 8)
        vt[((size_t)(b * NKV + kh) * HD + d0 + ty + j) * SEQ + t0 + tx] =
            __float2half(tile[tx][ty + j]);
}

__global__ void angles_kernel(float* __restrict__ cs, float* __restrict__ sn)
{
    const int i = blockIdx.x * blockDim.x + threadIdx.x;
    if (i >= SEQ * HD) return;
    const int d = i & (HD - 1);
    const int t = i >> 7;
    const double TWO_PI  = 6.283185307179586;
    const double INV_2PI = 0.15915494309189535;
    const double f   = exp(-9.210340371976184 * (double)d / 128.0);
    const double ang = (double)t * f;
    const double ar  = ang - floor(ang * INV_2PI) * TWO_PI;
    float sa, ca;
    sincosf((float)ar, &sa, &ca);
    cs[i] = ca;
    sn[i] = sa;
}

__global__ void delta_kernel(const float* __restrict__ delta,
                             float* __restrict__ cd, float* __restrict__ sd)
{
    const int i = blockIdx.x * blockDim.x + threadIdx.x;
    if (i >= NH * HD) return;
    float dl = delta[i];
    dl = fminf(fmaxf(dl, -6.2831855f), 0.0f);
    float s, c;
    sincosf(dl, &s, &c);
    cd[i] = c;
    sd[i] = s;
}

__device__ __forceinline__ float softplus_fast(float x)
{
    if (x > 15.0f) return x;
    return __logf(1.0f + __expf(x));
}

__global__ void encode_kernel(const float* __restrict__ q,
                              const float* __restrict__ k,
                              const float* __restrict__ cs,
                              const float* __restrict__ sn,
                              const float* __restrict__ cd,
                              const float* __restrict__ sd,
                              __half* __restrict__ qe,
                              __half* __restrict__ ke)
{
    const int i = blockIdx.x * blockDim.x + threadIdx.x;
    const int total = BSZ * NH * SEQ * HD;
    if (i >= total) return;

    const int d = i & (HD - 1);
    const int t = (i >> 7) & (SEQ - 1);
    const int h = (i >> 18) & (NH - 1);
    const int b = i >> 22;

    const float ca = cs[(t << 7) + d];
    const float sa = sn[(t << 7) + d];

    {
        float qv  = q[((size_t)(b * SEQ + t)) * (NH * HD) + h * HD + d];
        float mag = softplus_fast(qv);
        size_t o = (((size_t)(b * NH + h)) * SEQ + t) * DQK + d;
        qe[o]      = __float2half(mag * ca);
        qe[o + HD] = __float2half(mag * sa);
    }

    {
        const float c = cd[(h << 7) + d];
        const float s = sd[(h << 7) + d];
        const float ck = ca * c - sa * s;
        const float sk = sa * c + ca * s;
        float kv  = k[((size_t)(b * SEQ + t)) * (NKV * HD) + (h >> 1) * HD + d];
        float mag = softplus_fast(kv);
        size_t o = (((size_t)(b * NH + h)) * SEQ + t) * DQK + d;
        ke[o]      = __float2half(mag * ck);
        ke[o + HD] = __float2half(mag * sk);
    }
}

// ---------------------------------------------------------------------------
// fp16 GEMM core: 128x128x32 tile, 128 threads (4 warps, warp tile 64x64),
// ldmatrix fragment loads, 3-stage cp.async.
// ---------------------------------------------------------------------------
#define GASTR 40
#define G_STG_H (2 * 128 * GASTR)
#define G_STAGES 3
#define GEMM_SMEM_BYTES (G_STAGES * G_STG_H * 2)

__device__ __forceinline__ void gemm_tile_body(
    const __half* __restrict__ Ag, const __half* __restrict__ Bg,
    float* __restrict__ C, int N, int K, int row0, int col0, __half* smh)
{
    const int tid    = threadIdx.x;
    const int wid    = tid >> 5;
    const int lane   = tid & 31;
    const int g      = lane >> 2;
    const int t      = lane & 3;
    const int lane15 = lane & 15;
    const int lanehi = (lane >> 4) * 8;

    const int mbase = (wid & 1) * 64;
    const int nbase = (wid >> 1) * 64;

    const uint32_t smb   = (uint32_t)__cvta_generic_to_shared(smh);
    const uint32_t a_off = (uint32_t)((mbase + lane15) * GASTR + lanehi);
    const uint32_t b_off = (uint32_t)((nbase + lane15) * GASTR + lanehi);

    float acc[4][8][4];
    #pragma unroll
    for (int i = 0; i < 4; i++)
        #pragma unroll
        for (int j = 0; j < 8; j++)
            #pragma unroll
            for (int u = 0; u < 4; u++) acc[i][j][u] = 0.0f;

    const int kiters = K / 32;

    auto issue_stage = [&](int s, int it) {
        const int k0 = it * 32;
        unsigned sa = smb + (unsigned)s * (G_STG_H * 2u);
        unsigned sb = sa + 128u * GASTR * 2u;
        #pragma unroll
        for (int j = 0; j < 4; j++) {
            int c = tid + j * 128;              // 0..511
            int r  = c >> 2;                    // 0..127
            int ch = (c & 3) * 8;
            const __half* srca = Ag + (size_t)r * K + k0 + ch;
            asm volatile("cp.async.cg.shared.global [%0], [%1], 16;\n"
                         :: "r"(sa + (unsigned)(r * GASTR + ch) * 2u), "l"(srca));
            const __half* srcb = Bg + (size_t)r * K + k0 + ch;
            asm volatile("cp.async.cg.shared.global [%0], [%1], 16;\n"
                         :: "r"(sb + (unsigned)(r * GASTR + ch) * 2u), "l"(srcb));
        }
        asm volatile("cp.async.commit_group;\n");
    };

    issue_stage(0, 0);
    issue_stage(1, 1);

    for (int it = 0; it < kiters; it++) {
        if (it + 2 < kiters)
            issue_stage((it + 2) % G_STAGES, it + 2);
        else
            asm volatile("cp.async.commit_group;\n");
        asm volatile("cp.async.wait_group 2;\n");
        __syncthreads();

        const uint32_t sa = smb + (uint32_t)(it % G_STAGES) * (G_STG_H * 2u);
        const uint32_t sb = sa + 128u * GASTR * 2u;

        #pragma unroll
        for (int ks = 0; ks < 2; ks++) {
            const int kk = ks * 16;
            uint32_t af[4][4];
            #pragma unroll
            for (int mt = 0; mt < 4; mt++)
                LDSM_X4(af[mt][0], af[mt][1], af[mt][2], af[mt][3],
                        sa + (a_off + mt * 16 * GASTR + kk) * 2u);
            uint32_t bf[8][2];
            #pragma unroll
            for (int p = 0; p < 4; p++) {
                uint32_t r0, r1, r2, r3;
                LDSM_X4(r0, r1, r2, r3,
                        sb + (b_off + p * 16 * GASTR + kk) * 2u);
                bf[2 * p][0]     = r0;
                bf[2 * p + 1][0] = r1;
                bf[2 * p][1]     = r2;
                bf[2 * p + 1][1] = r3;
            }
            #pragma unroll
            for (int mt = 0; mt < 4; mt++)
                #pragma unroll
                for (int nt = 0; nt < 8; nt++)
                    MMA_F16(acc[mt][nt], af[mt], bf[nt]);
        }
        __syncthreads();
    }

    #pragma unroll
    for (int mt = 0; mt < 4; mt++) {
        #pragma unroll
        for (int nt = 0; nt < 8; nt++) {
            int row = row0 + mbase + mt * 16 + g;
            int col = col0 + nbase + nt * 8 + 2 * t;
            *(float2*)(C + (size_t)row * N + col) =
                make_float2(acc[mt][nt][0], acc[mt][nt][1]);
            *(float2*)(C + (size_t)(row + 8) * N + col) =
                make_float2(acc[mt][nt][2], acc[mt][nt][3]);
        }
    }
}

// Fused Q/K/V projection: grid.x = 16 (Q) + 8 (K) + 8 (V) N-tiles, grid.y = M tiles.
__global__ void __launch_bounds__(128)
gemm_qkv_kernel(const __half* __restrict__ A,
                const __half* __restrict__ Wq, float* __restrict__ Q,
                const __half* __restrict__ Wk, float* __restrict__ Kc,
                const __half* __restrict__ Wv, float* __restrict__ V,
                int M, int K)
{
    extern __shared__ __half smh[];
    const int bx = blockIdx.x;

    const __half* B;
    float* C;
    int N, xb;
    if (bx < 16)      { B = Wq; C = Q;  N = DM;       xb = bx; }
    else if (bx < 24) { B = Wk; C = Kc; N = NKV * HD; xb = bx - 16; }
    else              { B = Wv; C = V;  N = NKV * HD; xb = bx - 24; }

    gemm_tile_body(A + (size_t)blockIdx.y * 128 * K,
                   B + (size_t)xb * 128 * K,
                   C, N, K, blockIdx.y * 128, xb * 128, smh);
}

// Plain GEMM (Wo projection)
__global__ void __launch_bounds__(128)
gemm_h_kernel(const __half* __restrict__ A, const __half* __restrict__ B,
              float* __restrict__ C, int M, int N, int K)
{
    extern __shared__ __half smh[];
    gemm_tile_body(A + (size_t)blockIdx.y * 128 * K,
                   B + (size_t)blockIdx.x * 128 * K,
                   C, N, K, blockIdx.y * 128, blockIdx.x * 128, smh);
}

// ---------------------------------------------------------------------------
// fp16 causal flash attention. BM=128, BN=64, 256 threads (8 warps x 16 rows).
// QK k=256, PV k=64. V pre-transposed [d][T]. Double-buffered cp.async.
// ---------------------------------------------------------------------------
#define FBM 128
#define FBN 64
#define QSTR 264
#define KSTR 264
#define VSTR 72
#define PSTR 72

#define FL_Q_H (FBM * QSTR)
#define FL_K_H (2 * FBN * KSTR)
#define FL_V_H (2 * HD * VSTR)
#define FL_P_H (FBM * PSTR)
#define FLASH_SMEM_BYTES ((FL_Q_H + FL_K_H + FL_V_H + FL_P_H) * 2)

__global__ void __launch_bounds__(256)
flash_h_kernel(const __half* __restrict__ Qe, const __half* __restrict__ Ke,
               const __half* __restrict__ Vt, __half* __restrict__ Y)
{
    extern __shared__ __half smh[];
    __half* Ps = smh + FL_Q_H + FL_K_H + FL_V_H;

    const int qt = blockIdx.x;
    const int h  = blockIdx.y;
    const int b  = blockIdx.z;
    const int q0 = qt * FBM;

    const int tid    = threadIdx.x;
    const int wid    = tid >> 5;
    const int lane   = tid & 31;
    const int g      = lane >> 2;
    const int t      = lane & 3;
    const int lane15 = lane & 15;
    const int lanehi = (lane >> 4) * 8;
    const int r0     = wid * 16;

    const __half* qbase = Qe + (((size_t)(b * NH + h)) * SEQ + q0) * DQK;
    const __half* kbase = Ke + (((size_t)(b * NH + h)) * SEQ) * DQK;
    const __half* vbase = Vt + ((size_t)(b * NKV + (h >> 1)) * HD) * SEQ;

    const uint32_t smb  = (uint32_t)__cvta_generic_to_shared(smh);
    const uint32_t qs_b = smb;
    const uint32_t ks_b = smb + FL_Q_H * 2u;
    const uint32_t vs_b = smb + (FL_Q_H + FL_K_H) * 2u;
    const uint32_t ps_b = smb + (FL_Q_H + FL_K_H + FL_V_H) * 2u;

    const uint32_t q_off = (uint32_t)((r0 + lane15) * QSTR + lanehi);
    const uint32_t k_off = (uint32_t)(lane15 * KSTR + lanehi);
    const uint32_t v_off = (uint32_t)(lane15 * VSTR + lanehi);
    const uint32_t p_off = (uint32_t)((r0 + lane15) * PSTR + lanehi);

    // Q tile 128x256 halves = 4096 chunks, 16 iters of 256 threads
    {
        #pragma unroll
        for (int l = 0; l < 16; l++) {
            int i = l * 256 + tid;
            int r  = i >> 5;              // 0..127
            int c8 = (i & 31) * 8;
            const __half* src = qbase + (size_t)r * DQK + c8;
            asm volatile("cp.async.cg.shared.global [%0], [%1], 16;\n"
                         :: "r"(qs_b + (unsigned)(r * QSTR + c8) * 2u), "l"(src));
        }
        asm volatile("cp.async.commit_group;\n");
    }

    auto issue_kv = [&](int s, int kt) {
        const int k0 = kt * FBN;
        unsigned ks = ks_b + (unsigned)s * (FBN * KSTR * 2u);
        unsigned vs = vs_b + (unsigned)s * (HD * VSTR * 2u);
        #pragma unroll
        for (int l = 0; l < 8; l++) {       // K: 64x256 halves = 2048 chunks
            int i = l * 256 + tid;
            int r  = i >> 5;                // 0..63
            int c8 = (i & 31) * 8;
            const __half* src = kbase + (size_t)(k0 + r) * DQK + c8;
            asm volatile("cp.async.cg.shared.global [%0], [%1], 16;\n"
                         :: "r"(ks + (unsigned)(r * KSTR + c8) * 2u), "l"(src));
        }
        #pragma unroll
        for (int l = 0; l < 4; l++) {       // V: 128 d x 64 t halves = 1024 chunks
            int i = l * 256 + tid;
            int rd = i >> 3;                // 0..127
            int c8 = (i & 7) * 8;           // 0..56
            const __half* src = vbase + (size_t)rd * SEQ + k0 + c8;
            asm volatile("cp.async.cg.shared.global [%0], [%1], 16;\n"
                         :: "r"(vs + (unsigned)(rd * VSTR + c8) * 2u), "l"(src));
        }
        asm volatile("cp.async.commit_group;\n");
    };

    float m[2]    = { -3.0e38f, -3.0e38f };
    float lsum[2] = { 0.0f, 0.0f };
    float oacc[16][4];
    #pragma unroll
    for (int j = 0; j < 16; j++)
        #pragma unroll
        for (int u = 0; u < 4; u++) oacc[j][u] = 0.0f;

    const float scale = 0.08838834764831845f;
    const int ntl = 2 * qt + 2;

    issue_kv(0, 0);

    for (int kt = 0; kt < ntl; kt++) {
        const int k0 = kt * FBN;
        if (kt + 1 < ntl)
            issue_kv((kt + 1) & 1, kt + 1);
        else
            asm volatile("cp.async.commit_group;\n");
        asm volatile("cp.async.wait_group 1;\n");
        __syncthreads();

        const uint32_t ksb = ks_b + (uint32_t)(kt & 1) * (FBN * KSTR * 2u);
        const uint32_t vsb = vs_b + (uint32_t)(kt & 1) * (HD * VSTR * 2u);

        // ---- S = Q K^T (16x64 per warp, k=256) ----
        float sacc[8][4];
        #pragma unroll
        for (int j = 0; j < 8; j++)
            #pragma unroll
            for (int u = 0; u < 4; u++) sacc[j][u] = 0.0f;

        #pragma unroll
        for (int ks = 0; ks < 16; ks++) {
            const int kk = ks * 16;
            uint32_t a[4];
            LDSM_X4(a[0], a[1], a[2], a[3], qs_b + (q_off + kk) * 2u);
            uint32_t bf[8][2];
            #pragma unroll
            for (int p = 0; p < 4; p++) {
                uint32_t r0r, r1r, r2r, r3r;
                LDSM_X4(r0r, r1r, r2r, r3r,
                        ksb + (k_off + p * 16 * KSTR + kk) * 2u);
                bf[2 * p][0]     = r0r;
                bf[2 * p + 1][0] = r1r;
                bf[2 * p][1]     = r2r;
                bf[2 * p + 1][1] = r3r;
            }
            #pragma unroll
            for (int j = 0; j < 8; j++)
                MMA_F16(sacc[j], a, bf[j]);
        }

        // ---- online softmax (rows r0+g, r0+g+8; warp-local) ----
        const bool diag = (kt >= 2 * qt);
        #pragma unroll
        for (int hf = 0; hf < 2; hf++) {
            const int row = q0 + r0 + g + 8 * hf;
            float v[16];
            float mloc = -3.0e38f;
            #pragma unroll
            for (int j = 0; j < 8; j++) {
                #pragma unroll
                for (int c = 0; c < 2; c++) {
                    int col = k0 + 8 * j + 2 * t + c;
                    float sv = sacc[j][2 * hf + c] * scale;
                    if (diag && col > row) sv = -3.0e38f;
                    v[2 * j + c] = sv;
                    mloc = fmaxf(mloc, sv);
                }
            }
            mloc = fmaxf(mloc, __shfl_xor_sync(0xffffffffu, mloc, 1));
            mloc = fmaxf(mloc, __shfl_xor_sync(0xffffffffu, mloc, 2));
            float mn = fmaxf(m[hf], mloc);
            float alpha = __expf(m[hf] - mn);
            float rs = 0.0f;
            __half2 ph[8];
            #pragma unroll
            for (int j = 0; j < 8; j++) {
                float p0 = __expf(v[2 * j]     - mn);
                float p1 = __expf(v[2 * j + 1] - mn);
                __half2 h2 = __floats2half2_rn(p0, p1);
                ph[j] = h2;
                float2 pr = __half22float2(h2);
                rs += pr.x + pr.y;
            }
            rs += __shfl_xor_sync(0xffffffffu, rs, 1);
            rs += __shfl_xor_sync(0xffffffffu, rs, 2);
            lsum[hf] = lsum[hf] * alpha + rs;
            m[hf] = mn;
            #pragma unroll
            for (int j = 0; j < 16; j++) {
                oacc[j][2 * hf]     *= alpha;
                oacc[j][2 * hf + 1] *= alpha;
            }
            #pragma unroll
            for (int j = 0; j < 8; j++)
                *(__half2*)(Ps + (size_t)(r0 + g + 8 * hf) * PSTR
                            + 8 * j + 2 * t) = ph[j];
        }
        __syncwarp();

        // ---- O += P V (16x128 per warp, k=64) ----
        #pragma unroll
        for (int ks = 0; ks < 4; ks++) {
            const int kk = ks * 16;
            uint32_t a[4];
            LDSM_X4(a[0], a[1], a[2], a[3], ps_b + (p_off + kk) * 2u);
            #pragma unroll
            for (int p = 0; p < 8; p++) {
                uint32_t r0r, r1r, r2r, r3r;
                LDSM_X4(r0r, r1r, r2r, r3r,
                        vsb + (v_off + p * 16 * VSTR + kk) * 2u);
                uint32_t b0[2] = { r0r, r2r };
                uint32_t b1[2] = { r1r, r3r };
                MMA_F16(oacc[2 * p],     a, b0);
                MMA_F16(oacc[2 * p + 1], a, b1);
            }
        }
        __syncthreads();
    }

    // epilogue
    #pragma unroll
    for (int hf = 0; hf < 2; hf++) {
        const int row = q0 + r0 + g + 8 * hf;
        const float inv = 1.0f / lsum[hf];
        __half* yr = Y + ((size_t)b * SEQ + row) * DM + h * HD;
        #pragma unroll
        for (int j = 0; j < 16; j++)
            *(__half2*)(yr + 8 * j + 2 * t) =
                __floats2half2_rn(oacc[j][2 * hf] * inv,
                                  oacc[j][2 * hf + 1] * inv);
    }
}

// ---------------------------------------------------------------------------
// Launch
// ---------------------------------------------------------------------------
extern "C" void kernel_launch(void* const* d_in, const int* in_sizes, int n_in,
                              void* d_out, int out_size)
{
    const float* x     = (const float*)d_in[0];
    const float* Wq    = (const float*)d_in[1];
    const float* Wk    = (const float*)d_in[2];
    const float* Wv    = (const float*)d_in[3];
    const float* Wo    = (const float*)d_in[4];
    const float* delta = (const float*)d_in[5];
    float* out = (float*)d_out;

    float  *q_, *k_, *v_, *cs_, *sn_, *cd_, *sd_;
    __half *qe_, *ke_, *vt_, *yh_, *xh_, *wq_, *wk_, *wv_, *wo_;
    cudaGetSymbolAddress((void**)&q_,  g_q);
    cudaGetSymbolAddress((void**)&k_,  g_k);
    cudaGetSymbolAddress((void**)&v_,  g_v);
    cudaGetSymbolAddress((void**)&qe_, g_qe);
    cudaGetSymbolAddress((void**)&ke_, g_ke);
    cudaGetSymbolAddress((void**)&vt_, g_vt);
    cudaGetSymbolAddress((void**)&yh_, g_yh);
    cudaGetSymbolAddress((void**)&xh_, g_xh);
    cudaGetSymbolAddress((void**)&wq_, g_wq);
    cudaGetSymbolAddress((void**)&wk_, g_wk);
    cudaGetSymbolAddress((void**)&wv_, g_wv);
    cudaGetSymbolAddress((void**)&wo_, g_wo);
    cudaGetSymbolAddress((void**)&cs_, g_cs);
    cudaGetSymbolAddress((void**)&sn_, g_sn);
    cudaGetSymbolAddress((void**)&cd_, g_cd);
    cudaGetSymbolAddress((void**)&sd_, g_sd);

    const int M = BSZ * SEQ;   // 4096

    cudaFuncSetAttribute(gemm_qkv_kernel,
                         cudaFuncAttributeMaxDynamicSharedMemorySize,
                         GEMM_SMEM_BYTES);
    cudaFuncSetAttribute(gemm_h_kernel,
                         cudaFuncAttributeMaxDynamicSharedMemorySize,
                         GEMM_SMEM_BYTES);
    cudaFuncSetAttribute(flash_h_kernel,
                         cudaFuncAttributeMaxDynamicSharedMemorySize,
                         FLASH_SMEM_BYTES);

    // prep
    {
        int n = BSZ * SEQ * DM;
        f2h_kernel<<<(n / 4 + 255) / 256, 256>>>(x, xh_, n);
        dim3 blk(32, 8);
        transpose_h_kernel<<<dim3(DM / 32,       DM / 32), blk>>>(Wq, wq_, DM, DM);
        transpose_h_kernel<<<dim3(NKV * HD / 32, DM / 32), blk>>>(Wk, wk_, DM, NKV * HD);
        transpose_h_kernel<<<dim3(NKV * HD / 32, DM / 32), blk>>>(Wv, wv_, DM, NKV * HD);
        transpose_h_kernel<<<dim3(DM / 32,       DM / 32), blk>>>(Wo, wo_, DM, DM);
        angles_kernel<<<(SEQ * HD + 255) / 256, 256>>>(cs_, sn_);
        delta_kernel<<<(NH * HD + 255) / 256, 256>>>(delta, cd_, sd_);
    }

    // fused Q/K/V projections: one launch, 32 N-tiles x 32 M-tiles
    gemm_qkv_kernel<<<dim3(32, M / 128), 128, GEMM_SMEM_BYTES>>>(
        xh_, wq_, q_, wk_, k_, wv_, v_, M, DM);

    // encode + V transpose
    {
        const int total = BSZ * NH * SEQ * HD;
        encode_kernel<<<(total + 255) / 256, 256>>>(q_, k_, cs_, sn_, cd_, sd_,
                                                    qe_, ke_);
        vtrans_kernel<<<dim3(SEQ / 32, HD / 32, BSZ * NKV), dim3(32, 8)>>>(v_, vt_);
    }

    // flash attention
    flash_h_kernel<<<dim3(SEQ / FBM, NH, BSZ), 256, FLASH_SMEM_BYTES>>>(
        qe_, ke_, vt_, yh_);

    // output projection
    gemm_h_kernel<<<dim3(DM / 128, M / 128), 128, GEMM_SMEM_BYTES>>>(
        yh_, wo_, out, M, DM, DM);
}

// round 16
// speedup vs baseline: 1.0878x; 1.0159x over previous
#include <cuda_runtime.h>
#include <cuda_fp16.h>
#include <math.h>
#include <stdint.h>

// Problem constants
#define BSZ   2
#define SEQ   2048
#define DM    2048
#define NH    16
#define NKV   8
#define HD    128
#define DQK   256

// ---------------------------------------------------------------------------
// Scratch
// ---------------------------------------------------------------------------
__device__ float  g_q [BSZ * SEQ * NH  * HD];
__device__ float  g_k [BSZ * SEQ * NKV * HD];
__device__ float  g_v [BSZ * SEQ * NKV * HD];
__device__ __half g_qe[(size_t)BSZ * NH  * SEQ * DQK];
__device__ __half g_ke[(size_t)BSZ * NH  * SEQ * DQK];
__device__ __half g_vt[(size_t)BSZ * NKV * HD * SEQ];   // [b][kvh][d][T]
__device__ __half g_yh[BSZ * SEQ * NH * HD];
__device__ __half g_xh [BSZ * SEQ * DM];
__device__ __half g_wq [NH  * HD * DM];
__device__ __half g_wk [NKV * HD * DM];
__device__ __half g_wv [NKV * HD * DM];
__device__ __half g_wo [DM * NH * HD];
// phase tables
__device__ float g_cs [SEQ * HD];
__device__ float g_sn [SEQ * HD];
__device__ float g_cd [NH * HD];
__device__ float g_sd [NH * HD];

#define MMA_F16(d, a, b)                                                      \
    asm volatile(                                                             \
        "mma.sync.aligned.m16n8k16.row.col.f32.f16.f16.f32 "                  \
        "{%0,%1,%2,%3},{%4,%5,%6,%7},{%8,%9},{%0,%1,%2,%3};\n"                \
        : "+f"((d)[0]), "+f"((d)[1]), "+f"((d)[2]), "+f"((d)[3])              \
        : "r"((a)[0]), "r"((a)[1]), "r"((a)[2]), "r"((a)[3]),                 \
          "r"((b)[0]), "r"((b)[1]))

#define LDSM_X4(r0, r1, r2, r3, addr)                                         \
    asm volatile("ldmatrix.sync.aligned.m8n8.x4.shared.b16 "                  \
                 "{%0,%1,%2,%3}, [%4];"                                       \
                 : "=r"(r0), "=r"(r1), "=r"(r2), "=r"(r3) : "r"(addr))

// ---------------------------------------------------------------------------
// Prep kernels
// ---------------------------------------------------------------------------
__global__ void f2h_kernel(const float* __restrict__ in,
                           __half* __restrict__ out, int n)
{
    int i = (blockIdx.x * blockDim.x + threadIdx.x) * 4;
    if (i < n) {
        float4 v = *(const float4*)(in + i);
        __half2 h0 = __floats2half2_rn(v.x, v.y);
        __half2 h1 = __floats2half2_rn(v.z, v.w);
        uint2 u;
        u.x = *(uint32_t*)&h0;
        u.y = *(uint32_t*)&h1;
        *(uint2*)(out + i) = u;
    }
}

__global__ void transpose_h_kernel(const float* __restrict__ in,
                                   __half* __restrict__ out, int K, int N)
{
    __shared__ float tile[32][33];
    const int n0 = blockIdx.x * 32;
    const int k0 = blockIdx.y * 32;
    const int tx = threadIdx.x;
    const int ty = threadIdx.y;   // block (32, 8)
    #pragma unroll
    for (int j = 0; j < 32; j += 8)
        tile[ty + j][tx] = in[(size_t)(k0 + ty + j) * N + n0 + tx];
    __syncthreads();
    #pragma unroll
    for (int j = 0; j < 32; j += 8)
        out[(size_t)(n0 + ty + j) * K + k0 + tx] = __float2half(tile[tx][ty + j]);
}

__global__ void vtrans_kernel(const float* __restrict__ v,
                              __half* __restrict__ vt)
{
    __shared__ float tile[32][33];
    const int t0 = blockIdx.x * 32;
    const int d0 = blockIdx.y * 32;
    const int z  = blockIdx.z;
    const int b  = z / NKV;
    const int kh = z % NKV;
    const int tx = threadIdx.x;
    const int ty = threadIdx.y;   // block (32, 8)
    #pragma unroll
    for (int j = 0; j < 32; j += 8)
        tile[ty + j][tx] =
            v[((size_t)(b * SEQ + t0 + ty + j)) * (NKV * HD) + kh * HD + d0 + tx];
    __syncthreads();
    #pragma unroll
    for (int j = 0; j < 32; j += 8)
        vt[((size_t)(b * NKV + kh) * HD + d0 + ty + j) * SEQ + t0 + tx] =
            __float2half(tile[tx][ty + j]);
}

__global__ void angles_kernel(float* __restrict__ cs, float* __restrict__ sn)
{
    const int i = blockIdx.x * blockDim.x + threadIdx.x;
    if (i >= SEQ * HD) return;
    const int d = i & (HD - 1);
    const int t = i >> 7;
    const double TWO_PI  = 6.283185307179586;
    const double INV_2PI = 0.15915494309189535;
    const double f   = exp(-9.210340371976184 * (double)d / 128.0);
    const double ang = (double)t * f;
    const double ar  = ang - floor(ang * INV_2PI) * TWO_PI;
    float sa, ca;
    sincosf((float)ar, &sa, &ca);
    cs[i] = ca;
    sn[i] = sa;
}

__global__ void delta_kernel(const float* __restrict__ delta,
                             float* __restrict__ cd, float* __restrict__ sd)
{
    const int i = blockIdx.x * blockDim.x + threadIdx.x;
    if (i >= NH * HD) return;
    float dl = delta[i];
    dl = fminf(fmaxf(dl, -6.2831855f), 0.0f);
    float s, c;
    sincosf(dl, &s, &c);
    cd[i] = c;
    sd[i] = s;
}

__device__ __forceinline__ float softplus_fast(float x)
{
    if (x > 15.0f) return x;
    return __logf(1.0f + __expf(x));
}

__global__ void encode_kernel(const float* __restrict__ q,
                              const float* __restrict__ k,
                              const float* __restrict__ cs,
                              const float* __restrict__ sn,
                              const float* __restrict__ cd,
                              const float* __restrict__ sd,
                              __half* __restrict__ qe,
                              __half* __restrict__ ke)
{
    const int i = blockIdx.x * blockDim.x + threadIdx.x;
    const int total = BSZ * NH * SEQ * HD;
    if (i >= total) return;

    const int d = i & (HD - 1);
    const int t = (i >> 7) & (SEQ - 1);
    const int h = (i >> 18) & (NH - 1);
    const int b = i >> 22;

    const float ca = cs[(t << 7) + d];
    const float sa = sn[(t << 7) + d];

    {
        float qv  = q[((size_t)(b * SEQ + t)) * (NH * HD) + h * HD + d];
        float mag = softplus_fast(qv);
        size_t o = (((size_t)(b * NH + h)) * SEQ + t) * DQK + d;
        qe[o]      = __float2half(mag * ca);
        qe[o + HD] = __float2half(mag * sa);
    }

    {
        const float c = cd[(h << 7) + d];
        const float s = sd[(h << 7) + d];
        const float ck = ca * c - sa * s;
        const float sk = sa * c + ca * s;
        float kv  = k[((size_t)(b * SEQ + t)) * (NKV * HD) + (h >> 1) * HD + d];
        float mag = softplus_fast(kv);
        size_t o = (((size_t)(b * NH + h)) * SEQ + t) * DQK + d;
        ke[o]      = __float2half(mag * ck);
        ke[o + HD] = __float2half(mag * sk);
    }
}

// ---------------------------------------------------------------------------
// fp16 GEMM core: 128x128x32 tile, 128 threads (4 warps, warp tile 64x64),
// ldmatrix fragment loads, 3-stage cp.async.
// ---------------------------------------------------------------------------
#define GASTR 40
#define G_STG_H (2 * 128 * GASTR)
#define G_STAGES 3
#define GEMM_SMEM_BYTES (G_STAGES * G_STG_H * 2)

__device__ __forceinline__ void gemm_tile_body(
    const __half* __restrict__ Ag, const __half* __restrict__ Bg,
    float* __restrict__ C, int N, int K, int row0, int col0, __half* smh)
{
    const int tid    = threadIdx.x;
    const int wid    = tid >> 5;
    const int lane   = tid & 31;
    const int g      = lane >> 2;
    const int t      = lane & 3;
    const int lane15 = lane & 15;
    const int lanehi = (lane >> 4) * 8;

    const int mbase = (wid & 1) * 64;
    const int nbase = (wid >> 1) * 64;

    const uint32_t smb   = (uint32_t)__cvta_generic_to_shared(smh);
    const uint32_t a_off = (uint32_t)((mbase + lane15) * GASTR + lanehi);
    const uint32_t b_off = (uint32_t)((nbase + lane15) * GASTR + lanehi);

    float acc[4][8][4];
    #pragma unroll
    for (int i = 0; i < 4; i++)
        #pragma unroll
        for (int j = 0; j < 8; j++)
            #pragma unroll
            for (int u = 0; u < 4; u++) acc[i][j][u] = 0.0f;

    const int kiters = K / 32;

    auto issue_stage = [&](int s, int it) {
        const int k0 = it * 32;
        unsigned sa = smb + (unsigned)s * (G_STG_H * 2u);
        unsigned sb = sa + 128u * GASTR * 2u;
        #pragma unroll
        for (int j = 0; j < 4; j++) {
            int c = tid + j * 128;              // 0..511
            int r  = c >> 2;                    // 0..127
            int ch = (c & 3) * 8;
            const __half* srca = Ag + (size_t)r * K + k0 + ch;
            asm volatile("cp.async.cg.shared.global [%0], [%1], 16;\n"
                         :: "r"(sa + (unsigned)(r * GASTR + ch) * 2u), "l"(srca));
            const __half* srcb = Bg + (size_t)r * K + k0 + ch;
            asm volatile("cp.async.cg.shared.global [%0], [%1], 16;\n"
                         :: "r"(sb + (unsigned)(r * GASTR + ch) * 2u), "l"(srcb));
        }
        asm volatile("cp.async.commit_group;\n");
    };

    issue_stage(0, 0);
    issue_stage(1, 1);

    for (int it = 0; it < kiters; it++) {
        if (it + 2 < kiters)
            issue_stage((it + 2) % G_STAGES, it + 2);
        else
            asm volatile("cp.async.commit_group;\n");
        asm volatile("cp.async.wait_group 2;\n");
        __syncthreads();

        const uint32_t sa = smb + (uint32_t)(it % G_STAGES) * (G_STG_H * 2u);
        const uint32_t sb = sa + 128u * GASTR * 2u;

        #pragma unroll
        for (int ks = 0; ks < 2; ks++) {
            const int kk = ks * 16;
            uint32_t af[4][4];
            #pragma unroll
            for (int mt = 0; mt < 4; mt++)
                LDSM_X4(af[mt][0], af[mt][1], af[mt][2], af[mt][3],
                        sa + (a_off + mt * 16 * GASTR + kk) * 2u);
            uint32_t bf[8][2];
            #pragma unroll
            for (int p = 0; p < 4; p++) {
                uint32_t r0, r1, r2, r3;
                LDSM_X4(r0, r1, r2, r3,
                        sb + (b_off + p * 16 * GASTR + kk) * 2u);
                bf[2 * p][0]     = r0;
                bf[2 * p + 1][0] = r1;
                bf[2 * p][1]     = r2;
                bf[2 * p + 1][1] = r3;
            }
            #pragma unroll
            for (int mt = 0; mt < 4; mt++)
                #pragma unroll
                for (int nt = 0; nt < 8; nt++)
                    MMA_F16(acc[mt][nt], af[mt], bf[nt]);
        }
        __syncthreads();
    }

    #pragma unroll
    for (int mt = 0; mt < 4; mt++) {
        #pragma unroll
        for (int nt = 0; nt < 8; nt++) {
            int row = row0 + mbase + mt * 16 + g;
            int col = col0 + nbase + nt * 8 + 2 * t;
            *(float2*)(C + (size_t)row * N + col) =
                make_float2(acc[mt][nt][0], acc[mt][nt][1]);
            *(float2*)(C + (size_t)(row + 8) * N + col) =
                make_float2(acc[mt][nt][2], acc[mt][nt][3]);
        }
    }
}

// Fused Q/K/V projection: grid.x = 16 (Q) + 8 (K) + 8 (V) N-tiles, grid.y = M tiles.
__global__ void __launch_bounds__(128)
gemm_qkv_kernel(const __half* __restrict__ A,
                const __half* __restrict__ Wq, float* __restrict__ Q,
                const __half* __restrict__ Wk, float* __restrict__ Kc,
                const __half* __restrict__ Wv, float* __restrict__ V,
                int M, int K)
{
    extern __shared__ __half smh[];
    const int bx = blockIdx.x;

    const __half* B;
    float* C;
    int N, xb;
    if (bx < 16)      { B = Wq; C = Q;  N = DM;       xb = bx; }
    else if (bx < 24) { B = Wk; C = Kc; N = NKV * HD; xb = bx - 16; }
    else              { B = Wv; C = V;  N = NKV * HD; xb = bx - 24; }

    gemm_tile_body(A + (size_t)blockIdx.y * 128 * K,
                   B + (size_t)xb * 128 * K,
                   C, N, K, blockIdx.y * 128, xb * 128, smh);
}

// Plain GEMM (Wo projection)
__global__ void __launch_bounds__(128)
gemm_h_kernel(const __half* __restrict__ A, const __half* __restrict__ B,
              float* __restrict__ C, int M, int N, int K)
{
    extern __shared__ __half smh[];
    gemm_tile_body(A + (size_t)blockIdx.y * 128 * K,
                   B + (size_t)blockIdx.x * 128 * K,
                   C, N, K, blockIdx.y * 128, blockIdx.x * 128, smh);
}

// ---------------------------------------------------------------------------
// fp16 causal flash attention. BM=128, BN=64, 256 threads (8 warps x 16 rows).
// QK k=256, PV k=64. V pre-transposed [d][T]. Double-buffered cp.async.
// P kept in registers (S D-fragment == PV A-fragment layout). LPT block order.
// ---------------------------------------------------------------------------
#define FBM 128
#define FBN 64
#define QSTR 264
#define KSTR 264
#define VSTR 72

#define FL_Q_H (FBM * QSTR)
#define FL_K_H (2 * FBN * KSTR)
#define FL_V_H (2 * HD * VSTR)
#define FLASH_SMEM_BYTES ((FL_Q_H + FL_K_H + FL_V_H) * 2)

__global__ void __launch_bounds__(256)
flash_h_kernel(const __half* __restrict__ Qe, const __half* __restrict__ Ke,
               const __half* __restrict__ Vt, __half* __restrict__ Y)
{
    extern __shared__ __half smh[];

    const int qt = gridDim.x - 1 - blockIdx.x;   // LPT: heaviest blocks first
    const int h  = blockIdx.y;
    const int b  = blockIdx.z;
    const int q0 = qt * FBM;

    const int tid    = threadIdx.x;
    const int wid    = tid >> 5;
    const int lane   = tid & 31;
    const int g      = lane >> 2;
    const int t      = lane & 3;
    const int lane15 = lane & 15;
    const int lanehi = (lane >> 4) * 8;
    const int r0     = wid * 16;

    const __half* qbase = Qe + (((size_t)(b * NH + h)) * SEQ + q0) * DQK;
    const __half* kbase = Ke + (((size_t)(b * NH + h)) * SEQ) * DQK;
    const __half* vbase = Vt + ((size_t)(b * NKV + (h >> 1)) * HD) * SEQ;

    const uint32_t smb  = (uint32_t)__cvta_generic_to_shared(smh);
    const uint32_t qs_b = smb;
    const uint32_t ks_b = smb + FL_Q_H * 2u;
    const uint32_t vs_b = smb + (FL_Q_H + FL_K_H) * 2u;

    const uint32_t q_off = (uint32_t)((r0 + lane15) * QSTR + lanehi);
    const uint32_t k_off = (uint32_t)(lane15 * KSTR + lanehi);
    const uint32_t v_off = (uint32_t)(lane15 * VSTR + lanehi);

    // Q tile 128x256 halves = 4096 chunks, 16 iters of 256 threads
    {
        #pragma unroll
        for (int l = 0; l < 16; l++) {
            int i = l * 256 + tid;
            int r  = i >> 5;              // 0..127
            int c8 = (i & 31) * 8;
            const __half* src = qbase + (size_t)r * DQK + c8;
            asm volatile("cp.async.cg.shared.global [%0], [%1], 16;\n"
                         :: "r"(qs_b + (unsigned)(r * QSTR + c8) * 2u), "l"(src));
        }
        asm volatile("cp.async.commit_group;\n");
    }

    auto issue_kv = [&](int s, int kt) {
        const int k0 = kt * FBN;
        unsigned ks = ks_b + (unsigned)s * (FBN * KSTR * 2u);
        unsigned vs = vs_b + (unsigned)s * (HD * VSTR * 2u);
        #pragma unroll
        for (int l = 0; l < 8; l++) {       // K: 64x256 halves = 2048 chunks
            int i = l * 256 + tid;
            int r  = i >> 5;                // 0..63
            int c8 = (i & 31) * 8;
            const __half* src = kbase + (size_t)(k0 + r) * DQK + c8;
            asm volatile("cp.async.cg.shared.global [%0], [%1], 16;\n"
                         :: "r"(ks + (unsigned)(r * KSTR + c8) * 2u), "l"(src));
        }
        #pragma unroll
        for (int l = 0; l < 4; l++) {       // V: 128 d x 64 t halves = 1024 chunks
            int i = l * 256 + tid;
            int rd = i >> 3;                // 0..127
            int c8 = (i & 7) * 8;           // 0..56
            const __half* src = vbase + (size_t)rd * SEQ + k0 + c8;
            asm volatile("cp.async.cg.shared.global [%0], [%1], 16;\n"
                         :: "r"(vs + (unsigned)(rd * VSTR + c8) * 2u), "l"(src));
        }
        asm volatile("cp.async.commit_group;\n");
    };

    float m[2]    = { -3.0e38f, -3.0e38f };
    float lsum[2] = { 0.0f, 0.0f };
    float oacc[16][4];
    #pragma unroll
    for (int j = 0; j < 16; j++)
        #pragma unroll
        for (int u = 0; u < 4; u++) oacc[j][u] = 0.0f;

    const float scale = 0.08838834764831845f;
    const int ntl = 2 * qt + 2;

    issue_kv(0, 0);

    for (int kt = 0; kt < ntl; kt++) {
        const int k0 = kt * FBN;
        if (kt + 1 < ntl)
            issue_kv((kt + 1) & 1, kt + 1);
        else
            asm volatile("cp.async.commit_group;\n");
        asm volatile("cp.async.wait_group 1;\n");
        __syncthreads();

        const uint32_t ksb = ks_b + (uint32_t)(kt & 1) * (FBN * KSTR * 2u);
        const uint32_t vsb = vs_b + (uint32_t)(kt & 1) * (HD * VSTR * 2u);

        // ---- S = Q K^T (16x64 per warp, k=256) ----
        float sacc[8][4];
        #pragma unroll
        for (int j = 0; j < 8; j++)
            #pragma unroll
            for (int u = 0; u < 4; u++) sacc[j][u] = 0.0f;

        #pragma unroll
        for (int ks = 0; ks < 16; ks++) {
            const int kk = ks * 16;
            uint32_t a[4];
            LDSM_X4(a[0], a[1], a[2], a[3], qs_b + (q_off + kk) * 2u);
            uint32_t bf[8][2];
            #pragma unroll
            for (int p = 0; p < 4; p++) {
                uint32_t r0r, r1r, r2r, r3r;
                LDSM_X4(r0r, r1r, r2r, r3r,
                        ksb + (k_off + p * 16 * KSTR + kk) * 2u);
                bf[2 * p][0]     = r0r;
                bf[2 * p + 1][0] = r1r;
                bf[2 * p][1]     = r2r;
                bf[2 * p + 1][1] = r3r;
            }
            #pragma unroll
            for (int j = 0; j < 8; j++)
                MMA_F16(sacc[j], a, bf[j]);
        }

        // ---- online softmax; P stays in registers ----
        // S D-fragment: sacc[j][2*hf+c] = row (r0+g+8*hf), col (k0+8j+2t+c).
        // PV A-fragment for k-step ks needs exactly:
        //   a0 = row g    cols 16ks+2t..   -> ph[0][2ks]
        //   a1 = row g+8  same             -> ph[1][2ks]
        //   a2 = row g    cols 16ks+8+2t.. -> ph[0][2ks+1]
        //   a3 = row g+8  same             -> ph[1][2ks+1]
        const bool diag = (kt >= 2 * qt);
        uint32_t ph[2][8];
        #pragma unroll
        for (int hf = 0; hf < 2; hf++) {
            const int row = q0 + r0 + g + 8 * hf;
            float v[16];
            float mloc = -3.0e38f;
            #pragma unroll
            for (int j = 0; j < 8; j++) {
                #pragma unroll
                for (int c = 0; c < 2; c++) {
                    int col = k0 + 8 * j + 2 * t + c;
                    float sv = sacc[j][2 * hf + c] * scale;
                    if (diag && col > row) sv = -3.0e38f;
                    v[2 * j + c] = sv;
                    mloc = fmaxf(mloc, sv);
                }
            }
            mloc = fmaxf(mloc, __shfl_xor_sync(0xffffffffu, mloc, 1));
            mloc = fmaxf(mloc, __shfl_xor_sync(0xffffffffu, mloc, 2));
            float mn = fmaxf(m[hf], mloc);
            float alpha = __expf(m[hf] - mn);
            float rs = 0.0f;
            #pragma unroll
            for (int j = 0; j < 8; j++) {
                float p0 = __expf(v[2 * j]     - mn);
                float p1 = __expf(v[2 * j + 1] - mn);
                __half2 h2 = __floats2half2_rn(p0, p1);
                ph[hf][j] = *(uint32_t*)&h2;
                float2 pr = __half22float2(h2);
                rs += pr.x + pr.y;
            }
            rs += __shfl_xor_sync(0xffffffffu, rs, 1);
            rs += __shfl_xor_sync(0xffffffffu, rs, 2);
            lsum[hf] = lsum[hf] * alpha + rs;
            m[hf] = mn;
            #pragma unroll
            for (int j = 0; j < 16; j++) {
                oacc[j][2 * hf]     *= alpha;
                oacc[j][2 * hf + 1] *= alpha;
            }
        }

        // ---- O += P V (16x128 per warp, k=64), A fragments from registers ----
        #pragma unroll
        for (int ks = 0; ks < 4; ks++) {
            const int kk = ks * 16;
            uint32_t a[4];
            a[0] = ph[0][2 * ks];
            a[1] = ph[1][2 * ks];
            a[2] = ph[0][2 * ks + 1];
            a[3] = ph[1][2 * ks + 1];
            #pragma unroll
            for (int p = 0; p < 8; p++) {
                uint32_t r0r, r1r, r2r, r3r;
                LDSM_X4(r0r, r1r, r2r, r3r,
                        vsb + (v_off + p * 16 * VSTR + kk) * 2u);
                uint32_t b0[2] = { r0r, r2r };
                uint32_t b1[2] = { r1r, r3r };
                MMA_F16(oacc[2 * p],     a, b0);
                MMA_F16(oacc[2 * p + 1], a, b1);
            }
        }
        __syncthreads();
    }

    // epilogue
    #pragma unroll
    for (int hf = 0; hf < 2; hf++) {
        const int row = q0 + r0 + g + 8 * hf;
        const float inv = 1.0f / lsum[hf];
        __half* yr = Y + ((size_t)b * SEQ + row) * DM + h * HD;
        #pragma unroll
        for (int j = 0; j < 16; j++)
            *(__half2*)(yr + 8 * j + 2 * t) =
                __floats2half2_rn(oacc[j][2 * hf] * inv,
                                  oacc[j][2 * hf + 1] * inv);
    }
}

// ---------------------------------------------------------------------------
// Launch
// ---------------------------------------------------------------------------
extern "C" void kernel_launch(void* const* d_in, const int* in_sizes, int n_in,
                              void* d_out, int out_size)
{
    const float* x     = (const float*)d_in[0];
    const float* Wq    = (const float*)d_in[1];
    const float* Wk    = (const float*)d_in[2];
    const float* Wv    = (const float*)d_in[3];
    const float* Wo    = (const float*)d_in[4];
    const float* delta = (const float*)d_in[5];
    float* out = (float*)d_out;

    float  *q_, *k_, *v_, *cs_, *sn_, *cd_, *sd_;
    __half *qe_, *ke_, *vt_, *yh_, *xh_, *wq_, *wk_, *wv_, *wo_;
    cudaGetSymbolAddress((void**)&q_,  g_q);
    cudaGetSymbolAddress((void**)&k_,  g_k);
    cudaGetSymbolAddress((void**)&v_,  g_v);
    cudaGetSymbolAddress((void**)&qe_, g_qe);
    cudaGetSymbolAddress((void**)&ke_, g_ke);
    cudaGetSymbolAddress((void**)&vt_, g_vt);
    cudaGetSymbolAddress((void**)&yh_, g_yh);
    cudaGetSymbolAddress((void**)&xh_, g_xh);
    cudaGetSymbolAddress((void**)&wq_, g_wq);
    cudaGetSymbolAddress((void**)&wk_, g_wk);
    cudaGetSymbolAddress((void**)&wv_, g_wv);
    cudaGetSymbolAddress((void**)&wo_, g_wo);
    cudaGetSymbolAddress((void**)&cs_, g_cs);
    cudaGetSymbolAddress((void**)&sn_, g_sn);
    cudaGetSymbolAddress((void**)&cd_, g_cd);
    cudaGetSymbolAddress((void**)&sd_, g_sd);

    const int M = BSZ * SEQ;   // 4096

    cudaFuncSetAttribute(gemm_qkv_kernel,
                         cudaFuncAttributeMaxDynamicSharedMemorySize,
                         GEMM_SMEM_BYTES);
    cudaFuncSetAttribute(gemm_h_kernel,
                         cudaFuncAttributeMaxDynamicSharedMemorySize,
                         GEMM_SMEM_BYTES);
    cudaFuncSetAttribute(flash_h_kernel,
                         cudaFuncAttributeMaxDynamicSharedMemorySize,
                         FLASH_SMEM_BYTES);

    // prep
    {
        int n = BSZ * SEQ * DM;
        f2h_kernel<<<(n / 4 + 255) / 256, 256>>>(x, xh_, n);
        dim3 blk(32, 8);
        transpose_h_kernel<<<dim3(DM / 32,       DM / 32), blk>>>(Wq, wq_, DM, DM);
        transpose_h_kernel<<<dim3(NKV * HD / 32, DM / 32), blk>>>(Wk, wk_, DM, NKV * HD);
        transpose_h_kernel<<<dim3(NKV * HD / 32, DM / 32), blk>>>(Wv, wv_, DM, NKV * HD);
        transpose_h_kernel<<<dim3(DM / 32,       DM / 32), blk>>>(Wo, wo_, DM, DM);
        angles_kernel<<<(SEQ * HD + 255) / 256, 256>>>(cs_, sn_);
        delta_kernel<<<(NH * HD + 255) / 256, 256>>>(delta, cd_, sd_);
    }

    // fused Q/K/V projections: one launch, 32 N-tiles x 32 M-tiles
    gemm_qkv_kernel<<<dim3(32, M / 128), 128, GEMM_SMEM_BYTES>>>(
        xh_, wq_, q_, wk_, k_, wv_, v_, M, DM);

    // encode + V transpose
    {
        const int total = BSZ * NH * SEQ * HD;
        encode_kernel<<<(total + 255) / 256, 256>>>(q_, k_, cs_, sn_, cd_, sd_,
                                                    qe_, ke_);
        vtrans_kernel<<<dim3(SEQ / 32, HD / 32, BSZ * NKV), dim3(32, 8)>>>(v_, vt_);
    }

    // flash attention (LPT order inside kernel)
    flash_h_kernel<<<dim3(SEQ / FBM, NH, BSZ), 256, FLASH_SMEM_BYTES>>>(
        qe_, ke_, vt_, yh_);

    // output projection
    gemm_h_kernel<<<dim3(DM / 128, M / 128), 128, GEMM_SMEM_BYTES>>>(
        yh_, wo_, out, M, DM, DM);
}

// round 17
// speedup vs baseline: 1.1015x; 1.0125x over previous
#include <cuda_runtime.h>
#include <cuda_fp16.h>
#include <math.h>
#include <stdint.h>

// Problem constants
#define BSZ   2
#define SEQ   2048
#define DM    2048
#define NH    16
#define NKV   8
#define HD    128
#define DQK   256

// ---------------------------------------------------------------------------
// Scratch
// ---------------------------------------------------------------------------
__device__ float  g_q [BSZ * SEQ * NH  * HD];
__device__ float  g_k [BSZ * SEQ * NKV * HD];
__device__ float  g_v [BSZ * SEQ * NKV * HD];
__device__ __half g_qe[(size_t)BSZ * NH  * SEQ * DQK];
__device__ __half g_ke[(size_t)BSZ * NH  * SEQ * DQK];
__device__ __half g_vt[(size_t)BSZ * NKV * HD * SEQ];   // [b][kvh][d][T]
__device__ __half g_yh[BSZ * SEQ * NH * HD];
__device__ __half g_xh [BSZ * SEQ * DM];
__device__ __half g_wq [NH  * HD * DM];
__device__ __half g_wk [NKV * HD * DM];
__device__ __half g_wv [NKV * HD * DM];
__device__ __half g_wo [DM * NH * HD];
// phase tables
__device__ float g_cs [SEQ * HD];
__device__ float g_sn [SEQ * HD];
__device__ float g_cd [NH * HD];
__device__ float g_sd [NH * HD];

#define MMA_F16(d, a, b)                                                      \
    asm volatile(                                                             \
        "mma.sync.aligned.m16n8k16.row.col.f32.f16.f16.f32 "                  \
        "{%0,%1,%2,%3},{%4,%5,%6,%7},{%8,%9},{%0,%1,%2,%3};\n"                \
        : "+f"((d)[0]), "+f"((d)[1]), "+f"((d)[2]), "+f"((d)[3])              \
        : "r"((a)[0]), "r"((a)[1]), "r"((a)[2]), "r"((a)[3]),                 \
          "r"((b)[0]), "r"((b)[1]))

#define LDSM_X4(r0, r1, r2, r3, addr)                                         \
    asm volatile("ldmatrix.sync.aligned.m8n8.x4.shared.b16 "                  \
                 "{%0,%1,%2,%3}, [%4];"                                       \
                 : "=r"(r0), "=r"(r1), "=r"(r2), "=r"(r3) : "r"(addr))

// ---------------------------------------------------------------------------
// Prep kernels
// ---------------------------------------------------------------------------
__global__ void f2h_kernel(const float* __restrict__ in,
                           __half* __restrict__ out, int n)
{
    int i = (blockIdx.x * blockDim.x + threadIdx.x) * 4;
    if (i < n) {
        float4 v = *(const float4*)(in + i);
        __half2 h0 = __floats2half2_rn(v.x, v.y);
        __half2 h1 = __floats2half2_rn(v.z, v.w);
        uint2 u;
        u.x = *(uint32_t*)&h0;
        u.y = *(uint32_t*)&h1;
        *(uint2*)(out + i) = u;
    }
}

__global__ void transpose_h_kernel(const float* __restrict__ in,
                                   __half* __restrict__ out, int K, int N)
{
    __shared__ float tile[32][33];
    const int n0 = blockIdx.x * 32;
    const int k0 = blockIdx.y * 32;
    const int tx = threadIdx.x;
    const int ty = threadIdx.y;   // block (32, 8)
    #pragma unroll
    for (int j = 0; j < 32; j += 8)
        tile[ty + j][tx] = in[(size_t)(k0 + ty + j) * N + n0 + tx];
    __syncthreads();
    #pragma unroll
    for (int j = 0; j < 32; j += 8)
        out[(size_t)(n0 + ty + j) * K + k0 + tx] = __float2half(tile[tx][ty + j]);
}

__global__ void vtrans_kernel(const float* __restrict__ v,
                              __half* __restrict__ vt)
{
    __shared__ float tile[32][33];
    const int t0 = blockIdx.x * 32;
    const int d0 = blockIdx.y * 32;
    const int z  = blockIdx.z;
    const int b  = z / NKV;
    const int kh = z % NKV;
    const int tx = threadIdx.x;
    const int ty = threadIdx.y;   // block (32, 8)
    #pragma unroll
    for (int j = 0; j < 32; j += 8)
        tile[ty + j][tx] =
            v[((size_t)(b * SEQ + t0 + ty + j)) * (NKV * HD) + kh * HD + d0 + tx];
    __syncthreads();
    #pragma unroll
    for (int j = 0; j < 32; j += 8)
        vt[((size_t)(b * NKV + kh) * HD + d0 + ty + j) * SEQ + t0 + tx] =
            __float2half(tile[tx][ty + j]);
}

__global__ void angles_kernel(float* __restrict__ cs, float* __restrict__ sn)
{
    const int i = blockIdx.x * blockDim.x + threadIdx.x;
    if (i >= SEQ * HD) return;
    const int d = i & (HD - 1);
    const int t = i >> 7;
    const double TWO_PI  = 6.283185307179586;
    const double INV_2PI = 0.15915494309189535;
    const double f   = exp(-9.210340371976184 * (double)d / 128.0);
    const double ang = (double)t * f;
    const double ar  = ang - floor(ang * INV_2PI) * TWO_PI;
    float sa, ca;
    sincosf((float)ar, &sa, &ca);
    cs[i] = ca;
    sn[i] = sa;
}

__global__ void delta_kernel(const float* __restrict__ delta,
                             float* __restrict__ cd, float* __restrict__ sd)
{
    const int i = blockIdx.x * blockDim.x + threadIdx.x;
    if (i >= NH * HD) return;
    float dl = delta[i];
    dl = fminf(fmaxf(dl, -6.2831855f), 0.0f);
    float s, c;
    sincosf(dl, &s, &c);
    cd[i] = c;
    sd[i] = s;
}

__device__ __forceinline__ float softplus_fast(float x)
{
    if (x > 15.0f) return x;
    return __logf(1.0f + __expf(x));
}

__global__ void encode_kernel(const float* __restrict__ q,
                              const float* __restrict__ k,
                              const float* __restrict__ cs,
                              const float* __restrict__ sn,
                              const float* __restrict__ cd,
                              const float* __restrict__ sd,
                              __half* __restrict__ qe,
                              __half* __restrict__ ke)
{
    const int i = blockIdx.x * blockDim.x + threadIdx.x;
    const int total = BSZ * NH * SEQ * HD;
    if (i >= total) return;

    const int d = i & (HD - 1);
    const int t = (i >> 7) & (SEQ - 1);
    const int h = (i >> 18) & (NH - 1);
    const int b = i >> 22;

    const float ca = cs[(t << 7) + d];
    const float sa = sn[(t << 7) + d];

    {
        float qv  = q[((size_t)(b * SEQ + t)) * (NH * HD) + h * HD + d];
        float mag = softplus_fast(qv);
        size_t o = (((size_t)(b * NH + h)) * SEQ + t) * DQK + d;
        qe[o]      = __float2half(mag * ca);
        qe[o + HD] = __float2half(mag * sa);
    }

    {
        const float c = cd[(h << 7) + d];
        const float s = sd[(h << 7) + d];
        const float ck = ca * c - sa * s;
        const float sk = sa * c + ca * s;
        float kv  = k[((size_t)(b * SEQ + t)) * (NKV * HD) + (h >> 1) * HD + d];
        float mag = softplus_fast(kv);
        size_t o = (((size_t)(b * NH + h)) * SEQ + t) * DQK + d;
        ke[o]      = __float2half(mag * ck);
        ke[o + HD] = __float2half(mag * sk);
    }
}

// ---------------------------------------------------------------------------
// fp16 GEMM core: 128x128x32 tile, 128 threads (4 warps, warp tile 64x64),
// ldmatrix fragment loads, 3-stage cp.async.
// ---------------------------------------------------------------------------
#define GASTR 40
#define G_STG_H (2 * 128 * GASTR)
#define G_STAGES 3
#define GEMM_SMEM_BYTES (G_STAGES * G_STG_H * 2)

__device__ __forceinline__ void gemm_tile_body(
    const __half* __restrict__ Ag, const __half* __restrict__ Bg,
    float* __restrict__ C, int N, int K, int row0, int col0, __half* smh)
{
    const int tid    = threadIdx.x;
    const int wid    = tid >> 5;
    const int lane   = tid & 31;
    const int g      = lane >> 2;
    const int t      = lane & 3;
    const int lane15 = lane & 15;
    const int lanehi = (lane >> 4) * 8;

    const int mbase = (wid & 1) * 64;
    const int nbase = (wid >> 1) * 64;

    const uint32_t smb   = (uint32_t)__cvta_generic_to_shared(smh);
    const uint32_t a_off = (uint32_t)((mbase + lane15) * GASTR + lanehi);
    const uint32_t b_off = (uint32_t)((nbase + lane15) * GASTR + lanehi);

    float acc[4][8][4];
    #pragma unroll
    for (int i = 0; i < 4; i++)
        #pragma unroll
        for (int j = 0; j < 8; j++)
            #pragma unroll
            for (int u = 0; u < 4; u++) acc[i][j][u] = 0.0f;

    const int kiters = K / 32;

    auto issue_stage = [&](int s, int it) {
        const int k0 = it * 32;
        unsigned sa = smb + (unsigned)s * (G_STG_H * 2u);
        unsigned sb = sa + 128u * GASTR * 2u;
        #pragma unroll
        for (int j = 0; j < 4; j++) {
            int c = tid + j * 128;              // 0..511
            int r  = c >> 2;                    // 0..127
            int ch = (c & 3) * 8;
            const __half* srca = Ag + (size_t)r * K + k0 + ch;
            asm volatile("cp.async.cg.shared.global [%0], [%1], 16;\n"
                         :: "r"(sa + (unsigned)(r * GASTR + ch) * 2u), "l"(srca));
            const __half* srcb = Bg + (size_t)r * K + k0 + ch;
            asm volatile("cp.async.cg.shared.global [%0], [%1], 16;\n"
                         :: "r"(sb + (unsigned)(r * GASTR + ch) * 2u), "l"(srcb));
        }
        asm volatile("cp.async.commit_group;\n");
    };

    issue_stage(0, 0);
    issue_stage(1, 1);

    for (int it = 0; it < kiters; it++) {
        if (it + 2 < kiters)
            issue_stage((it + 2) % G_STAGES, it + 2);
        else
            asm volatile("cp.async.commit_group;\n");
        asm volatile("cp.async.wait_group 2;\n");
        __syncthreads();

        const uint32_t sa = smb + (uint32_t)(it % G_STAGES) * (G_STG_H * 2u);
        const uint32_t sb = sa + 128u * GASTR * 2u;

        #pragma unroll
        for (int ks = 0; ks < 2; ks++) {
            const int kk = ks * 16;
            uint32_t af[4][4];
            #pragma unroll
            for (int mt = 0; mt < 4; mt++)
                LDSM_X4(af[mt][0], af[mt][1], af[mt][2], af[mt][3],
                        sa + (a_off + mt * 16 * GASTR + kk) * 2u);
            uint32_t bf[8][2];
            #pragma unroll
            for (int p = 0; p < 4; p++) {
                uint32_t r0, r1, r2, r3;
                LDSM_X4(r0, r1, r2, r3,
                        sb + (b_off + p * 16 * GASTR + kk) * 2u);
                bf[2 * p][0]     = r0;
                bf[2 * p + 1][0] = r1;
                bf[2 * p][1]     = r2;
                bf[2 * p + 1][1] = r3;
            }
            #pragma unroll
            for (int mt = 0; mt < 4; mt++)
                #pragma unroll
                for (int nt = 0; nt < 8; nt++)
                    MMA_F16(acc[mt][nt], af[mt], bf[nt]);
        }
        __syncthreads();
    }

    #pragma unroll
    for (int mt = 0; mt < 4; mt++) {
        #pragma unroll
        for (int nt = 0; nt < 8; nt++) {
            int row = row0 + mbase + mt * 16 + g;
            int col = col0 + nbase + nt * 8 + 2 * t;
            *(float2*)(C + (size_t)row * N + col) =
                make_float2(acc[mt][nt][0], acc[mt][nt][1]);
            *(float2*)(C + (size_t)(row + 8) * N + col) =
                make_float2(acc[mt][nt][2], acc[mt][nt][3]);
        }
    }
}

// Fused Q/K/V projection: grid.x = 16 (Q) + 8 (K) + 8 (V) N-tiles, grid.y = M tiles.
__global__ void __launch_bounds__(128)
gemm_qkv_kernel(const __half* __restrict__ A,
                const __half* __restrict__ Wq, float* __restrict__ Q,
                const __half* __restrict__ Wk, float* __restrict__ Kc,
                const __half* __restrict__ Wv, float* __restrict__ V,
                int M, int K)
{
    extern __shared__ __half smh[];
    const int bx = blockIdx.x;

    const __half* B;
    float* C;
    int N, xb;
    if (bx < 16)      { B = Wq; C = Q;  N = DM;       xb = bx; }
    else if (bx < 24) { B = Wk; C = Kc; N = NKV * HD; xb = bx - 16; }
    else              { B = Wv; C = V;  N = NKV * HD; xb = bx - 24; }

    gemm_tile_body(A + (size_t)blockIdx.y * 128 * K,
                   B + (size_t)xb * 128 * K,
                   C, N, K, blockIdx.y * 128, xb * 128, smh);
}

// Plain GEMM (Wo projection)
__global__ void __launch_bounds__(128)
gemm_h_kernel(const __half* __restrict__ A, const __half* __restrict__ B,
              float* __restrict__ C, int M, int N, int K)
{
    extern __shared__ __half smh[];
    gemm_tile_body(A + (size_t)blockIdx.y * 128 * K,
                   B + (size_t)blockIdx.x * 128 * K,
                   C, N, K, blockIdx.y * 128, blockIdx.x * 128, smh);
}

// ---------------------------------------------------------------------------
// fp16 causal flash attention. BM=128, BN=64, 256 threads (8 warps x 16 rows).
// QK k=256, PV k=64. V pre-transposed [d][T]. Double-buffered cp.async.
// P kept in registers. LPT block order.
// ---------------------------------------------------------------------------
#define FBM 128
#define FBN 64
#define QSTR 264
#define KSTR 264
#define VSTR 72

#define FL_Q_H (FBM * QSTR)
#define FL_K_H (2 * FBN * KSTR)
#define FL_V_H (2 * HD * VSTR)
#define FLASH_SMEM_BYTES ((FL_Q_H + FL_K_H + FL_V_H) * 2)

__global__ void __launch_bounds__(256)
flash_h_kernel(const __half* __restrict__ Qe, const __half* __restrict__ Ke,
               const __half* __restrict__ Vt, __half* __restrict__ Y)
{
    extern __shared__ __half smh[];

    const int qt = gridDim.x - 1 - blockIdx.x;   // LPT: heaviest blocks first
    const int h  = blockIdx.y;
    const int b  = blockIdx.z;
    const int q0 = qt * FBM;

    const int tid    = threadIdx.x;
    const int wid    = tid >> 5;
    const int lane   = tid & 31;
    const int g      = lane >> 2;
    const int t      = lane & 3;
    const int lane15 = lane & 15;
    const int lanehi = (lane >> 4) * 8;
    const int r0     = wid * 16;

    const __half* qbase = Qe + (((size_t)(b * NH + h)) * SEQ + q0) * DQK;
    const __half* kbase = Ke + (((size_t)(b * NH + h)) * SEQ) * DQK;
    const __half* vbase = Vt + ((size_t)(b * NKV + (h >> 1)) * HD) * SEQ;

    const uint32_t smb  = (uint32_t)__cvta_generic_to_shared(smh);
    const uint32_t qs_b = smb;
    const uint32_t ks_b = smb + FL_Q_H * 2u;
    const uint32_t vs_b = smb + (FL_Q_H + FL_K_H) * 2u;

    const uint32_t q_off = (uint32_t)((r0 + lane15) * QSTR + lanehi);
    const uint32_t k_off = (uint32_t)(lane15 * KSTR + lanehi);
    const uint32_t v_off = (uint32_t)(lane15 * VSTR + lanehi);

    // Q tile 128x256 halves = 4096 chunks, 16 iters of 256 threads
    {
        #pragma unroll
        for (int l = 0; l < 16; l++) {
            int i = l * 256 + tid;
            int r  = i >> 5;              // 0..127
            int c8 = (i & 31) * 8;
            const __half* src = qbase + (size_t)r * DQK + c8;
            asm volatile("cp.async.cg.shared.global [%0], [%1], 16;\n"
                         :: "r"(qs_b + (unsigned)(r * QSTR + c8) * 2u), "l"(src));
        }
        asm volatile("cp.async.commit_group;\n");
    }

    auto issue_kv = [&](int s, int kt) {
        const int k0 = kt * FBN;
        unsigned ks = ks_b + (unsigned)s * (FBN * KSTR * 2u);
        unsigned vs = vs_b + (unsigned)s * (HD * VSTR * 2u);
        #pragma unroll
        for (int l = 0; l < 8; l++) {       // K: 64x256 halves = 2048 chunks
            int i = l * 256 + tid;
            int r  = i >> 5;                // 0..63
            int c8 = (i & 31) * 8;
            const __half* src = kbase + (size_t)(k0 + r) * DQK + c8;
            asm volatile("cp.async.cg.shared.global [%0], [%1], 16;\n"
                         :: "r"(ks + (unsigned)(r * KSTR + c8) * 2u), "l"(src));
        }
        #pragma unroll
        for (int l = 0; l < 4; l++) {       // V: 128 d x 64 t halves = 1024 chunks
            int i = l * 256 + tid;
            int rd = i >> 3;                // 0..127
            int c8 = (i & 7) * 8;           // 0..56
            const __half* src = vbase + (size_t)rd * SEQ + k0 + c8;
            asm volatile("cp.async.cg.shared.global [%0], [%1], 16;\n"
                         :: "r"(vs + (unsigned)(rd * VSTR + c8) * 2u), "l"(src));
        }
        asm volatile("cp.async.commit_group;\n");
    };

    float m[2]    = { -3.0e38f, -3.0e38f };
    float lsum[2] = { 0.0f, 0.0f };
    float oacc[16][4];
    #pragma unroll
    for (int j = 0; j < 16; j++)
        #pragma unroll
        for (int u = 0; u < 4; u++) oacc[j][u] = 0.0f;

    const float scale = 0.08838834764831845f;
    const int ntl = 2 * qt + 2;

    issue_kv(0, 0);

    for (int kt = 0; kt < ntl; kt++) {
        const int k0 = kt * FBN;
        if (kt + 1 < ntl)
            issue_kv((kt + 1) & 1, kt + 1);
        else
            asm volatile("cp.async.commit_group;\n");
        asm volatile("cp.async.wait_group 1;\n");
        __syncthreads();

        const uint32_t ksb = ks_b + (uint32_t)(kt & 1) * (FBN * KSTR * 2u);
        const uint32_t vsb = vs_b + (uint32_t)(kt & 1) * (HD * VSTR * 2u);

        // ---- S = Q K^T (16x64 per warp, k=256) ----
        float sacc[8][4];
        #pragma unroll
        for (int j = 0; j < 8; j++)
            #pragma unroll
            for (int u = 0; u < 4; u++) sacc[j][u] = 0.0f;

        #pragma unroll
        for (int ks = 0; ks < 16; ks++) {
            const int kk = ks * 16;
            uint32_t a[4];
            LDSM_X4(a[0], a[1], a[2], a[3], qs_b + (q_off + kk) * 2u);
            uint32_t bf[8][2];
            #pragma unroll
            for (int p = 0; p < 4; p++) {
                uint32_t r0r, r1r, r2r, r3r;
                LDSM_X4(r0r, r1r, r2r, r3r,
                        ksb + (k_off + p * 16 * KSTR + kk) * 2u);
                bf[2 * p][0]     = r0r;
                bf[2 * p + 1][0] = r1r;
                bf[2 * p][1]     = r2r;
                bf[2 * p + 1][1] = r3r;
            }
            #pragma unroll
            for (int j = 0; j < 8; j++)
                MMA_F16(sacc[j], a, bf[j]);
        }

        // ---- online softmax; P stays in registers ----
        const bool diag = (kt >= 2 * qt);
        uint32_t ph[2][8];
        #pragma unroll
        for (int hf = 0; hf < 2; hf++) {
            const int row = q0 + r0 + g + 8 * hf;
            float v[16];
            float mloc = -3.0e38f;
            #pragma unroll
            for (int j = 0; j < 8; j++) {
                #pragma unroll
                for (int c = 0; c < 2; c++) {
                    int col = k0 + 8 * j + 2 * t + c;
                    float sv = sacc[j][2 * hf + c] * scale;
                    if (diag && col > row) sv = -3.0e38f;
                    v[2 * j + c] = sv;
                    mloc = fmaxf(mloc, sv);
                }
            }
            mloc = fmaxf(mloc, __shfl_xor_sync(0xffffffffu, mloc, 1));
            mloc = fmaxf(mloc, __shfl_xor_sync(0xffffffffu, mloc, 2));
            float mn = fmaxf(m[hf], mloc);
            float alpha = __expf(m[hf] - mn);
            float rs = 0.0f;
            #pragma unroll
            for (int j = 0; j < 8; j++) {
                float p0 = __expf(v[2 * j]     - mn);
                float p1 = __expf(v[2 * j + 1] - mn);
                __half2 h2 = __floats2half2_rn(p0, p1);
                ph[hf][j] = *(uint32_t*)&h2;
                float2 pr = __half22float2(h2);
                rs += pr.x + pr.y;
            }
            rs += __shfl_xor_sync(0xffffffffu, rs, 1);
            rs += __shfl_xor_sync(0xffffffffu, rs, 2);
            lsum[hf] = lsum[hf] * alpha + rs;
            m[hf] = mn;
            #pragma unroll
            for (int j = 0; j < 16; j++) {
                oacc[j][2 * hf]     *= alpha;
                oacc[j][2 * hf + 1] *= alpha;
            }
        }

        // ---- O += P V (16x128 per warp, k=64), A fragments from registers ----
        #pragma unroll
        for (int ks = 0; ks < 4; ks++) {
            const int kk = ks * 16;
            uint32_t a[4];
            a[0] = ph[0][2 * ks];
            a[1] = ph[1][2 * ks];
            a[2] = ph[0][2 * ks + 1];
            a[3] = ph[1][2 * ks + 1];
            #pragma unroll
            for (int p = 0; p < 8; p++) {
                uint32_t r0r, r1r, r2r, r3r;
                LDSM_X4(r0r, r1r, r2r, r3r,
                        vsb + (v_off + p * 16 * VSTR + kk) * 2u);
                uint32_t b0[2] = { r0r, r2r };
                uint32_t b1[2] = { r1r, r3r };
                MMA_F16(oacc[2 * p],     a, b0);
                MMA_F16(oacc[2 * p + 1], a, b1);
            }
        }
        __syncthreads();
    }

    // epilogue
    #pragma unroll
    for (int hf = 0; hf < 2; hf++) {
        const int row = q0 + r0 + g + 8 * hf;
        const float inv = 1.0f / lsum[hf];
        __half* yr = Y + ((size_t)b * SEQ + row) * DM + h * HD;
        #pragma unroll
        for (int j = 0; j < 16; j++)
            *(__half2*)(yr + 8 * j + 2 * t) =
                __floats2half2_rn(oacc[j][2 * hf] * inv,
                                  oacc[j][2 * hf + 1] * inv);
    }
}

// ---------------------------------------------------------------------------
// Launch: multi-stream fork-join DAG (graph-capturable via events)
// ---------------------------------------------------------------------------
extern "C" void kernel_launch(void* const* d_in, const int* in_sizes, int n_in,
                              void* d_out, int out_size)
{
    const float* x     = (const float*)d_in[0];
    const float* Wq    = (const float*)d_in[1];
    const float* Wk    = (const float*)d_in[2];
    const float* Wv    = (const float*)d_in[3];
    const float* Wo    = (const float*)d_in[4];
    const float* delta = (const float*)d_in[5];
    float* out = (float*)d_out;

    float  *q_, *k_, *v_, *cs_, *sn_, *cd_, *sd_;
    __half *qe_, *ke_, *vt_, *yh_, *xh_, *wq_, *wk_, *wv_, *wo_;
    cudaGetSymbolAddress((void**)&q_,  g_q);
    cudaGetSymbolAddress((void**)&k_,  g_k);
    cudaGetSymbolAddress((void**)&v_,  g_v);
    cudaGetSymbolAddress((void**)&qe_, g_qe);
    cudaGetSymbolAddress((void**)&ke_, g_ke);
    cudaGetSymbolAddress((void**)&vt_, g_vt);
    cudaGetSymbolAddress((void**)&yh_, g_yh);
    cudaGetSymbolAddress((void**)&xh_, g_xh);
    cudaGetSymbolAddress((void**)&wq_, g_wq);
    cudaGetSymbolAddress((void**)&wk_, g_wk);
    cudaGetSymbolAddress((void**)&wv_, g_wv);
    cudaGetSymbolAddress((void**)&wo_, g_wo);
    cudaGetSymbolAddress((void**)&cs_, g_cs);
    cudaGetSymbolAddress((void**)&sn_, g_sn);
    cudaGetSymbolAddress((void**)&cd_, g_cd);
    cudaGetSymbolAddress((void**)&sd_, g_sd);

    const int M = BSZ * SEQ;   // 4096

    static bool init_done = false;
    static cudaStream_t s1, s2, s3;
    static cudaEvent_t eFork, eTW, eAD, eQKV, eVT, eWO;
    if (!init_done) {
        cudaStreamCreateWithFlags(&s1, cudaStreamNonBlocking);
        cudaStreamCreateWithFlags(&s2, cudaStreamNonBlocking);
        cudaStreamCreateWithFlags(&s3, cudaStreamNonBlocking);
        cudaEventCreateWithFlags(&eFork, cudaEventDisableTiming);
        cudaEventCreateWithFlags(&eTW,   cudaEventDisableTiming);
        cudaEventCreateWithFlags(&eAD,   cudaEventDisableTiming);
        cudaEventCreateWithFlags(&eQKV,  cudaEventDisableTiming);
        cudaEventCreateWithFlags(&eVT,   cudaEventDisableTiming);
        cudaEventCreateWithFlags(&eWO,   cudaEventDisableTiming);
        cudaFuncSetAttribute(gemm_qkv_kernel,
                             cudaFuncAttributeMaxDynamicSharedMemorySize,
                             GEMM_SMEM_BYTES);
        cudaFuncSetAttribute(gemm_h_kernel,
                             cudaFuncAttributeMaxDynamicSharedMemorySize,
                             GEMM_SMEM_BYTES);
        cudaFuncSetAttribute(flash_h_kernel,
                             cudaFuncAttributeMaxDynamicSharedMemorySize,
                             FLASH_SMEM_BYTES);
        init_done = true;
    }

    dim3 tblk(32, 8);

    // Fork: side streams branch from the main (capture) stream.
    cudaEventRecord(eFork, 0);
    cudaStreamWaitEvent(s1, eFork, 0);
    cudaStreamWaitEvent(s2, eFork, 0);

    // s1: Wq/Wk/Wv transposes, then phase tables.
    transpose_h_kernel<<<dim3(DM / 32,       DM / 32), tblk, 0, s1>>>(Wq, wq_, DM, DM);
    transpose_h_kernel<<<dim3(NKV * HD / 32, DM / 32), tblk, 0, s1>>>(Wk, wk_, DM, NKV * HD);
    transpose_h_kernel<<<dim3(NKV * HD / 32, DM / 32), tblk, 0, s1>>>(Wv, wv_, DM, NKV * HD);
    cudaEventRecord(eTW, s1);
    angles_kernel<<<(SEQ * HD + 255) / 256, 256, 0, s1>>>(cs_, sn_);
    delta_kernel<<<(NH * HD + 255) / 256, 256, 0, s1>>>(delta, cd_, sd_);
    cudaEventRecord(eAD, s1);

    // s2: Wo transpose (needed only before the final GEMM).
    transpose_h_kernel<<<dim3(DM / 32, DM / 32), tblk, 0, s2>>>(Wo, wo_, DM, DM);
    cudaEventRecord(eWO, s2);

    // main: x -> half (concurrent with s1/s2)
    {
        int n = BSZ * SEQ * DM;
        f2h_kernel<<<(n / 4 + 255) / 256, 256>>>(x, xh_, n);
    }

    // main: fused Q/K/V projections (needs xh + wq/wk/wv)
    cudaStreamWaitEvent(0, eTW, 0);
    gemm_qkv_kernel<<<dim3(32, M / 128), 128, GEMM_SMEM_BYTES>>>(
        xh_, wq_, q_, wk_, k_, wv_, v_, M, DM);
    cudaEventRecord(eQKV, 0);

    // s3: V transpose (concurrent with encode on main)
    cudaStreamWaitEvent(s3, eQKV, 0);
    vtrans_kernel<<<dim3(SEQ / 32, HD / 32, BSZ * NKV), tblk, 0, s3>>>(v_, vt_);
    cudaEventRecord(eVT, s3);

    // main: encode (needs q/k + tables)
    cudaStreamWaitEvent(0, eAD, 0);
    {
        const int total = BSZ * NH * SEQ * HD;
        encode_kernel<<<(total + 255) / 256, 256>>>(q_, k_, cs_, sn_, cd_, sd_,
                                                    qe_, ke_);
    }

    // main: flash attention (needs qe/ke + vt)
    cudaStreamWaitEvent(0, eVT, 0);
    flash_h_kernel<<<dim3(SEQ / FBM, NH, BSZ), 256, FLASH_SMEM_BYTES>>>(
        qe_, ke_, vt_, yh_);

    // main: output projection (needs y + wo)
    cudaStreamWaitEvent(0, eWO, 0);
    gemm_h_kernel<<<dim3(DM / 128, M / 128), 128, GEMM_SMEM_BYTES>>>(
        yh_, wo_, out, M, DM, DM);
}